// round 6
// baseline (speedup 1.0000x reference)
#include <cuda_runtime.h>

// ============================================================================
// EquivariantSpatialConv: fused 3x3 replicate-pad depthwise spatial average
// + fully-connected CG tensor product (irreps 1x4e + 1x6e) + residual.
//
// R6 (= R5 fixed): TP split into two single-output passes to cut live regs
// (~72 -> ~60) enabling __launch_bounds__(128, 8) -> 8 CTAs/SM. CG tensors
// are namespace-scope inline constexpr variable templates (fixes the nvcc
// "run-time storage" error for constexpr locals in function templates).
// ============================================================================

#define DEVHOST __host__ __device__

// ---------------- compile-time scalar math ----------------
DEVHOST constexpr double cfact(int n) {
    double r = 1.0;
    for (int i = 2; i <= n; ++i) r *= (double)i;
    return r;
}

DEVHOST constexpr double csqrt(double x) {
    if (x <= 0.0) return 0.0;
    double g = x > 1.0 ? x : 1.0;
    for (int it = 0; it < 48; ++it) g = 0.5 * (g + x / g);
    return g;
}

struct CD { double re, im; };
DEVHOST constexpr CD cmul(CD a, CD b) {
    return CD{a.re * b.re - a.im * b.im, a.re * b.im + a.im * b.re};
}
DEVHOST constexpr CD cconj(CD a) { return CD{a.re, -a.im}; }

DEVHOST constexpr double su2_cg(int j1, int j2, int j3, int m1, int m2, int m3) {
    if (m3 != m1 + m2) return 0.0;
    if (m1 < -j1 || m1 > j1 || m2 < -j2 || m2 > j2 || m3 < -j3 || m3 > j3) return 0.0;
    double pref0 = (2.0 * j3 + 1.0) * cfact(j1 + j2 - j3) * cfact(j1 - j2 + j3) *
                   cfact(-j1 + j2 + j3) / cfact(j1 + j2 + j3 + 1);
    double pref = csqrt(pref0 * cfact(j3 + m3) * cfact(j3 - m3) * cfact(j1 - m1) *
                        cfact(j1 + m1) * cfact(j2 - m2) * cfact(j2 + m2));
    int kmin = 0;
    if (-(j3 - j2 + m1) > kmin) kmin = -(j3 - j2 + m1);
    if (-(j3 - j1 - m2) > kmin) kmin = -(j3 - j1 - m2);
    int kmax = j1 + j2 - j3;
    if (j1 - m1 < kmax) kmax = j1 - m1;
    if (j2 + m2 < kmax) kmax = j2 + m2;
    double s = 0.0;
    for (int k = kmin; k <= kmax; ++k) {
        double d = cfact(k) * cfact(j1 + j2 - j3 - k) * cfact(j1 - m1 - k) *
                   cfact(j2 + m2 - k) * cfact(j3 - j2 + m1 + k) * cfact(j3 - j1 - m2 + k);
        s += ((k & 1) ? -1.0 : 1.0) / d;
    }
    return pref * s;
}

DEVHOST constexpr CD qent(int l, int r, int c) {
    constexpr double S2 = 0.70710678118654752440;
    int m = r - l;
    CD v{0.0, 0.0};
    if (m < 0) {
        if (c == l - m)      v = CD{S2, 0.0};
        else if (c == l + m) v = CD{0.0, -S2};
    } else if (m == 0) {
        if (c == l) v = CD{1.0, 0.0};
    } else {
        double sg = (m & 1) ? -1.0 : 1.0;
        if (c == l + m)      v = CD{sg * S2, 0.0};
        else if (c == l - m) v = CD{0.0, sg * S2};
    }
    int ph = l & 3;
    CD f = (ph == 0) ? CD{1, 0} : (ph == 1) ? CD{0, -1} : (ph == 2) ? CD{-1, 0} : CD{0, 1};
    return cmul(v, f);
}

DEVHOST constexpr double real_cg_entry(int l1, int l2, int l3, int a, int b, int c) {
    int d1 = a >= l1 ? a - l1 : l1 - a;
    int d2 = b >= l2 ? b - l2 : l2 - b;
    int d3 = c >= l3 ? c - l3 : l3 - c;
    CD sum{0.0, 0.0};
    int ni = d1 ? 2 : 1;
    int nk = d2 ? 2 : 1;
    for (int si = 0; si < ni; ++si) {
        int i = d1 ? (si ? l1 + d1 : l1 - d1) : l1;
        int m1 = i - l1;
        CD q1 = qent(l1, i, a);
        for (int sk = 0; sk < nk; ++sk) {
            int k = d2 ? (sk ? l2 + d2 : l2 - d2) : l2;
            int m2 = k - l2;
            int m3 = m1 + m2;
            if (m3 < -l3 || m3 > l3) continue;
            int am3 = m3 < 0 ? -m3 : m3;
            if (am3 != d3) continue;
            int n = l3 + m3;
            CD q2 = qent(l2, k, b);
            CD q3 = cconj(qent(l3, c, n));
            double C = su2_cg(l1, l2, l3, m1, m2, m3);
            CD t = cmul(cmul(q1, q2), q3);
            sum.re += t.re * C;
            sum.im += t.im * C;
        }
    }
    return sum.re;
}

template <int L1, int L2, int L3>
struct CGT {
    float v[2 * L1 + 1][2 * L2 + 1][2 * L3 + 1];
};

template <int L1, int L2, int L3>
DEVHOST constexpr CGT<L1, L2, L3> make_cg() {
    double tmp[2 * L1 + 1][2 * L2 + 1][2 * L3 + 1] = {};
    double ss = 0.0;
    for (int a = 0; a < 2 * L1 + 1; ++a)
        for (int b = 0; b < 2 * L2 + 1; ++b)
            for (int c = 0; c < 2 * L3 + 1; ++c) {
                double e = real_cg_entry(L1, L2, L3, a, b, c);
                tmp[a][b][c] = e;
                ss += e * e;
            }
    double inv = 1.0 / csqrt(ss);
    CGT<L1, L2, L3> r{};
    for (int a = 0; a < 2 * L1 + 1; ++a)
        for (int b = 0; b < 2 * L2 + 1; ++b)
            for (int c = 0; c < 2 * L3 + 1; ++c)
                r.v[a][b][c] = (float)(tmp[a][b][c] * inv);
    return r;
}

// Namespace-scope constexpr CG tensors: static storage, valid in constant
// expressions from any lambda depth (unlike constexpr locals in templates).
template <int L1, int L2, int L3>
inline constexpr CGT<L1, L2, L3> CG = make_cg<L1, L2, L3>();

// ---------------- compile-time unrolling helpers ----------------
template <int V> struct IC { static constexpr int value = V; };

template <int N, int I = 0, class F>
__device__ __forceinline__ void sfor(F&& f) {
    if constexpr (I < N) {
        f(IC<I>{});
        sfor<N, I + 1>(static_cast<F&&>(f));
    }
}

template <class T>
DEVHOST constexpr bool rowany(const T& t, int a, int b, int dk) {
    for (int k = 0; k < dk; ++k)
        if (t.v[a][b][k] != 0.0f) return true;
    return false;
}
template <class T>
DEVHOST constexpr bool rowany2(const T& t, int a, int b, int dk) {
    for (int k = 0; k < dk; ++k)
        if (t.v[a][b][k] != 0.0f || t.v[b][a][k] != 0.0f) return true;
    return false;
}
template <class T>
DEVHOST constexpr bool symk(const T& t, int a, int b, int dk) {
    for (int k = 0; k < dk; ++k)
        if (t.v[a][b][k] != t.v[b][a][k]) return false;
    return true;
}
template <class TA, class TB>
DEVHOST constexpr bool eqk(const TA& A, int i, int j, const TB& B, int bi, int bj, int dk) {
    for (int k = 0; k < dk; ++k)
        if (A.v[i][j][k] != B.v[bi][bj][k]) return false;
    return true;
}

// ---------------- packed f32x2 helpers ----------------
__device__ __forceinline__ float2 f2fma(float2 a, float2 b, float2 c) {
    float2 d;
    asm("fma.rn.f32x2 %0, %1, %2, %3;"
        : "=l"(*reinterpret_cast<unsigned long long*>(&d))
        : "l"(*reinterpret_cast<unsigned long long*>(&a)),
          "l"(*reinterpret_cast<unsigned long long*>(&b)),
          "l"(*reinterpret_cast<unsigned long long*>(&c)));
    return d;
}
__device__ __forceinline__ float2 f2mul(float2 a, float2 b) {
    float2 d;
    asm("mul.rn.f32x2 %0, %1, %2;"
        : "=l"(*reinterpret_cast<unsigned long long*>(&d))
        : "l"(*reinterpret_cast<unsigned long long*>(&a)),
          "l"(*reinterpret_cast<unsigned long long*>(&b)));
    return d;
}

// ---------------- single-output tensor-product passes ----------------
// Diagonal block (L,L,L3): symmetry-folded; acc has 2*L3+1 entries.
template <int L, int O, int L3>
__device__ __forceinline__ void tp_diag_one(const float* __restrict__ x1,
                                            const float* __restrict__ x2,
                                            float* __restrict__ acc, float w) {
    constexpr int D = 2 * L + 1;
    constexpr int DK = 2 * L3 + 1;
    sfor<D>([&](auto I) {
        constexpr int i = decltype(I)::value;
        sfor<D>([&](auto J) {
            constexpr int j = decltype(J)::value;
            if constexpr (j >= i) {
                if constexpr (rowany2(CG<L, L, L3>, i, j, DK)) {
                    if constexpr (i == j) {
                        float t = (x1[O + i] * x2[O + i]) * w;
                        sfor<DK>([&](auto K) {
                            constexpr int k = decltype(K)::value;
                            constexpr float cv = CG<L, L, L3>.v[i][i][k];
                            if constexpr (cv != 0.0f) acc[k] = __fmaf_rn(cv, t, acc[k]);
                        });
                    } else if constexpr (symk(CG<L, L, L3>, i, j, DK)) {
                        float s = __fmaf_rn(x1[O + j], x2[O + i], x1[O + i] * x2[O + j]);
                        float t = s * w;
                        sfor<DK>([&](auto K) {
                            constexpr int k = decltype(K)::value;
                            constexpr float cv = CG<L, L, L3>.v[i][j][k];
                            if constexpr (cv != 0.0f) acc[k] = __fmaf_rn(cv, t, acc[k]);
                        });
                    } else {
                        float t1 = (x1[O + i] * x2[O + j]) * w;
                        float t2 = (x1[O + j] * x2[O + i]) * w;
                        sfor<DK>([&](auto K) {
                            constexpr int k = decltype(K)::value;
                            constexpr float c1 = CG<L, L, L3>.v[i][j][k];
                            constexpr float c2 = CG<L, L, L3>.v[j][i][k];
                            if constexpr (c1 != 0.0f) acc[k] = __fmaf_rn(c1, t1, acc[k]);
                            if constexpr (c2 != 0.0f) acc[k] = __fmaf_rn(c2, t2, acc[k]);
                        });
                    }
                }
            }
        });
    });
}

// Cross block: paths (4,6,L3) weight wA and (6,4,L3) weight wB, merged when
// the CG tensors coincide under exchange (verified at compile time).
template <int L3>
__device__ __forceinline__ void tp_cross_one(const float* __restrict__ x1,
                                             const float* __restrict__ x2,
                                             float* __restrict__ acc,
                                             float wA, float wB) {
    constexpr int DK = 2 * L3 + 1;
    sfor<9>([&](auto I) {
        constexpr int i = decltype(I)::value;
        sfor<13>([&](auto J) {
            constexpr int j = decltype(J)::value;
            constexpr bool la = rowany(CG<4, 6, L3>, i, j, DK);
            constexpr bool lb = rowany(CG<6, 4, L3>, j, i, DK);
            if constexpr (la || lb) {
                float p1 = x1[i] * x2[9 + j];      // (4,6,L3)
                float p2 = x2[i] * x1[9 + j];      // (6,4,L3)
                if constexpr (la && lb && eqk(CG<4, 6, L3>, i, j, CG<6, 4, L3>, j, i, DK)) {
                    float u = __fmaf_rn(wB, p2, p1 * wA);
                    sfor<DK>([&](auto K) {
                        constexpr int k = decltype(K)::value;
                        constexpr float cv = CG<4, 6, L3>.v[i][j][k];
                        if constexpr (cv != 0.0f) acc[k] = __fmaf_rn(cv, u, acc[k]);
                    });
                } else {
                    if constexpr (la) {
                        float t1 = p1 * wA;
                        sfor<DK>([&](auto K) {
                            constexpr int k = decltype(K)::value;
                            constexpr float cv = CG<4, 6, L3>.v[i][j][k];
                            if constexpr (cv != 0.0f) acc[k] = __fmaf_rn(cv, t1, acc[k]);
                        });
                    }
                    if constexpr (lb) {
                        float t2 = p2 * wB;
                        sfor<DK>([&](auto K) {
                            constexpr int k = decltype(K)::value;
                            constexpr float cv = CG<6, 4, L3>.v[j][i][k];
                            if constexpr (cv != 0.0f) acc[k] = __fmaf_rn(cv, t2, acc[k]);
                        });
                    }
                }
            }
        });
    });
}

// ---------------- kernel ----------------
constexpr int H = 768, W = 768;
constexpr int TX = 32, TY = 4;             // 128-thread tile
constexpr int NT = TX * TY;                // 128
constexpr int HTX = TX + 2, HTY = TY + 2;  // 34 x 6 haloed tile
constexpr int NPIX = HTX * HTY;            // 204
constexpr int NPAIR = 11;                  // 22 channels as 11 float2 pairs

__global__ void __launch_bounds__(NT, 8) eq_spatial_tp_kernel(
    const float* __restrict__ f4, const float* __restrict__ f6,
    const float* __restrict__ sw, const float* __restrict__ wp,
    float* __restrict__ out4, float* __restrict__ out6) {
    // channel-pair-major: tile[p][pix]; lane-consecutive pix -> conflict-free LDS.64
    __shared__ float2 tile[NPAIR * NPIX];

    const int tid = threadIdx.x;
    const int bx = blockIdx.x, by = blockIdx.y;
    const int gx0 = bx * TX - 1, gy0 = by * TY - 1;

    // Cooperative haloed-tile load with replicate clamping.
#pragma unroll 4
    for (int idx = tid; idx < NPAIR * NPIX; idx += NT) {
        int p = idx / NPIX, pix = idx - p * NPIX;
        int r = pix / HTX, c = pix - r * HTX;
        int gy = gy0 + r; gy = gy < 0 ? 0 : (gy > H - 1 ? H - 1 : gy);
        int gx = gx0 + c; gx = gx < 0 ? 0 : (gx > W - 1 ? W - 1 : gx);
        int g = gy * W + gx;
        int ch = 2 * p;
        float v0 = (ch < 9) ? f4[g * 9 + ch] : f6[g * 13 + (ch - 9)];
        float v1 = (ch + 1 < 9) ? f4[g * 9 + ch + 1] : f6[g * 13 + (ch + 1 - 9)];
        tile[idx] = make_float2(v0, v1);
    }
    __syncthreads();

    float2 swp[9];
#pragma unroll
    for (int q = 0; q < 9; ++q) {
        float s = sw[q];
        swp[q] = make_float2(s, s);
    }
    float wcomb[8];
#pragma unroll
    for (int p = 0; p < 8; ++p) wcomb[p] = 0.5f * wp[p];  // ALPHA = 1/sqrt(4)

    const int tx = tid & 31, ty = tid >> 5;

    // x1 = center features; x2 = weighted 3x3 neighbor average (packed f32x2)
    __align__(8) float x1[22], x2[22];
    float2* x1v = reinterpret_cast<float2*>(x1);
    float2* x2v = reinterpret_cast<float2*>(x2);
    {
        const int cpix = (ty + 1) * HTX + (tx + 1);
#pragma unroll
        for (int p = 0; p < NPAIR; ++p) {
            x1v[p] = tile[p * NPIX + cpix];
            x2v[p] = f2mul(swp[4], x1v[p]);
        }
    }
#pragma unroll
    for (int dy = 0; dy < 3; ++dy)
#pragma unroll
        for (int dx = 0; dx < 3; ++dx) {
            if (dy == 1 && dx == 1) continue;
            const int npix = (ty + dy) * HTX + (tx + dx);
            const float2 wq = swp[dy * 3 + dx];
#pragma unroll
            for (int p = 0; p < NPAIR; ++p)
                x2v[p] = f2fma(wq, tile[p * NPIX + npix], x2v[p]);
        }

    const int gy = by * TY + ty, gx = bx * TX + tx;
    const int g = gy * W + gx;

    // ---- pass A: l3 = 4 output (paths c=0), residual folded ----
    {
        float acc4[9];
#pragma unroll
        for (int k = 0; k < 9; ++k) acc4[k] = x1[k];
        tp_diag_one<4, 0, 4>(x1, x2, acc4, wcomb[0]);
        tp_cross_one<4>(x1, x2, acc4, wcomb[2], wcomb[4]);
        tp_diag_one<6, 9, 4>(x1, x2, acc4, wcomb[6]);
#pragma unroll
        for (int k = 0; k < 9; ++k) out4[g * 9 + k] = acc4[k];
    }

    // ---- pass B: l3 = 6 output (paths c=1), residual folded ----
    {
        float acc6[13];
#pragma unroll
        for (int k = 0; k < 13; ++k) acc6[k] = x1[9 + k];
        tp_diag_one<4, 0, 6>(x1, x2, acc6, wcomb[1]);
        tp_cross_one<6>(x1, x2, acc6, wcomb[3], wcomb[5]);
        tp_diag_one<6, 9, 6>(x1, x2, acc6, wcomb[7]);
#pragma unroll
        for (int k = 0; k < 13; ++k) out6[g * 13 + k] = acc6[k];
    }
}

extern "C" void kernel_launch(void* const* d_in, const int* in_sizes, int n_in,
                              void* d_out, int out_size) {
    const float* f4 = (const float*)d_in[0];
    const float* f6 = (const float*)d_in[1];
    const float* sw = (const float*)d_in[2];  // spatial_weights [3,3]
    const float* wp = (const float*)d_in[3];  // w_paths [8]
    float* out = (float*)d_out;
    const size_t N = (size_t)H * W;

    dim3 grid(W / TX, H / TY);  // 24 x 192
    eq_spatial_tp_kernel<<<grid, NT>>>(f4, f6, sw, wp, out, out + N * 9);
}

// round 7
// speedup vs baseline: 3.3653x; 3.3653x over previous
#include <cuda_runtime.h>
#include <cstdint>

// ============================================================================
// EquivariantSpatialConv: fused 3x3 replicate-pad depthwise spatial average
// + fully-connected CG tensor product (irreps 1x4e + 1x6e) + residual.
//
// R7: persistent CTAs (888 = 6/SM x 148, all resident) + double-buffered
// cp.async tile prefetch: tile t+888 streams into buffer B while buffer A is
// computed, hiding the load phase entirely. TP = R4's single-pass merged
// blocks (no reg cap -> no spills). CG tensors are namespace-scope constexpr.
// ============================================================================

#define DEVHOST __host__ __device__

// ---------------- compile-time scalar math ----------------
DEVHOST constexpr double cfact(int n) {
    double r = 1.0;
    for (int i = 2; i <= n; ++i) r *= (double)i;
    return r;
}

DEVHOST constexpr double csqrt(double x) {
    if (x <= 0.0) return 0.0;
    double g = x > 1.0 ? x : 1.0;
    for (int it = 0; it < 48; ++it) g = 0.5 * (g + x / g);
    return g;
}

struct CD { double re, im; };
DEVHOST constexpr CD cmul(CD a, CD b) {
    return CD{a.re * b.re - a.im * b.im, a.re * b.im + a.im * b.re};
}
DEVHOST constexpr CD cconj(CD a) { return CD{a.re, -a.im}; }

DEVHOST constexpr double su2_cg(int j1, int j2, int j3, int m1, int m2, int m3) {
    if (m3 != m1 + m2) return 0.0;
    if (m1 < -j1 || m1 > j1 || m2 < -j2 || m2 > j2 || m3 < -j3 || m3 > j3) return 0.0;
    double pref0 = (2.0 * j3 + 1.0) * cfact(j1 + j2 - j3) * cfact(j1 - j2 + j3) *
                   cfact(-j1 + j2 + j3) / cfact(j1 + j2 + j3 + 1);
    double pref = csqrt(pref0 * cfact(j3 + m3) * cfact(j3 - m3) * cfact(j1 - m1) *
                        cfact(j1 + m1) * cfact(j2 - m2) * cfact(j2 + m2));
    int kmin = 0;
    if (-(j3 - j2 + m1) > kmin) kmin = -(j3 - j2 + m1);
    if (-(j3 - j1 - m2) > kmin) kmin = -(j3 - j1 - m2);
    int kmax = j1 + j2 - j3;
    if (j1 - m1 < kmax) kmax = j1 - m1;
    if (j2 + m2 < kmax) kmax = j2 + m2;
    double s = 0.0;
    for (int k = kmin; k <= kmax; ++k) {
        double d = cfact(k) * cfact(j1 + j2 - j3 - k) * cfact(j1 - m1 - k) *
                   cfact(j2 + m2 - k) * cfact(j3 - j2 + m1 + k) * cfact(j3 - j1 - m2 + k);
        s += ((k & 1) ? -1.0 : 1.0) / d;
    }
    return pref * s;
}

DEVHOST constexpr CD qent(int l, int r, int c) {
    constexpr double S2 = 0.70710678118654752440;
    int m = r - l;
    CD v{0.0, 0.0};
    if (m < 0) {
        if (c == l - m)      v = CD{S2, 0.0};
        else if (c == l + m) v = CD{0.0, -S2};
    } else if (m == 0) {
        if (c == l) v = CD{1.0, 0.0};
    } else {
        double sg = (m & 1) ? -1.0 : 1.0;
        if (c == l + m)      v = CD{sg * S2, 0.0};
        else if (c == l - m) v = CD{0.0, sg * S2};
    }
    int ph = l & 3;
    CD f = (ph == 0) ? CD{1, 0} : (ph == 1) ? CD{0, -1} : (ph == 2) ? CD{-1, 0} : CD{0, 1};
    return cmul(v, f);
}

DEVHOST constexpr double real_cg_entry(int l1, int l2, int l3, int a, int b, int c) {
    int d1 = a >= l1 ? a - l1 : l1 - a;
    int d2 = b >= l2 ? b - l2 : l2 - b;
    int d3 = c >= l3 ? c - l3 : l3 - c;
    CD sum{0.0, 0.0};
    int ni = d1 ? 2 : 1;
    int nk = d2 ? 2 : 1;
    for (int si = 0; si < ni; ++si) {
        int i = d1 ? (si ? l1 + d1 : l1 - d1) : l1;
        int m1 = i - l1;
        CD q1 = qent(l1, i, a);
        for (int sk = 0; sk < nk; ++sk) {
            int k = d2 ? (sk ? l2 + d2 : l2 - d2) : l2;
            int m2 = k - l2;
            int m3 = m1 + m2;
            if (m3 < -l3 || m3 > l3) continue;
            int am3 = m3 < 0 ? -m3 : m3;
            if (am3 != d3) continue;
            int n = l3 + m3;
            CD q2 = qent(l2, k, b);
            CD q3 = cconj(qent(l3, c, n));
            double C = su2_cg(l1, l2, l3, m1, m2, m3);
            CD t = cmul(cmul(q1, q2), q3);
            sum.re += t.re * C;
            sum.im += t.im * C;
        }
    }
    return sum.re;
}

template <int L1, int L2, int L3>
struct CGT {
    float v[2 * L1 + 1][2 * L2 + 1][2 * L3 + 1];
};

template <int L1, int L2, int L3>
DEVHOST constexpr CGT<L1, L2, L3> make_cg() {
    double tmp[2 * L1 + 1][2 * L2 + 1][2 * L3 + 1] = {};
    double ss = 0.0;
    for (int a = 0; a < 2 * L1 + 1; ++a)
        for (int b = 0; b < 2 * L2 + 1; ++b)
            for (int c = 0; c < 2 * L3 + 1; ++c) {
                double e = real_cg_entry(L1, L2, L3, a, b, c);
                tmp[a][b][c] = e;
                ss += e * e;
            }
    double inv = 1.0 / csqrt(ss);
    CGT<L1, L2, L3> r{};
    for (int a = 0; a < 2 * L1 + 1; ++a)
        for (int b = 0; b < 2 * L2 + 1; ++b)
            for (int c = 0; c < 2 * L3 + 1; ++c)
                r.v[a][b][c] = (float)(tmp[a][b][c] * inv);
    return r;
}

// Namespace-scope constexpr CG tensors (static storage: usable in constant
// expressions from any lambda depth inside function templates).
template <int L1, int L2, int L3>
inline constexpr CGT<L1, L2, L3> CG = make_cg<L1, L2, L3>();

// ---------------- compile-time unrolling helpers ----------------
template <int V> struct IC { static constexpr int value = V; };

template <int N, int I = 0, class F>
__device__ __forceinline__ void sfor(F&& f) {
    if constexpr (I < N) {
        f(IC<I>{});
        sfor<N, I + 1>(static_cast<F&&>(f));
    }
}

template <class T>
DEVHOST constexpr bool rowany(const T& t, int a, int b, int dk) {
    for (int k = 0; k < dk; ++k)
        if (t.v[a][b][k] != 0.0f) return true;
    return false;
}
template <class T>
DEVHOST constexpr bool rowany2(const T& t, int a, int b, int dk) {
    for (int k = 0; k < dk; ++k)
        if (t.v[a][b][k] != 0.0f || t.v[b][a][k] != 0.0f) return true;
    return false;
}
template <class T>
DEVHOST constexpr bool symk(const T& t, int a, int b, int dk) {
    for (int k = 0; k < dk; ++k)
        if (t.v[a][b][k] != t.v[b][a][k]) return false;
    return true;
}
template <class TA, class TB>
DEVHOST constexpr bool eqk(const TA& A, int i, int j, const TB& B, int bi, int bj, int dk) {
    for (int k = 0; k < dk; ++k)
        if (A.v[i][j][k] != B.v[bi][bj][k]) return false;
    return true;
}

// ---------------- packed f32x2 + cp.async helpers ----------------
__device__ __forceinline__ float2 f2fma(float2 a, float2 b, float2 c) {
    float2 d;
    asm("fma.rn.f32x2 %0, %1, %2, %3;"
        : "=l"(*reinterpret_cast<unsigned long long*>(&d))
        : "l"(*reinterpret_cast<unsigned long long*>(&a)),
          "l"(*reinterpret_cast<unsigned long long*>(&b)),
          "l"(*reinterpret_cast<unsigned long long*>(&c)));
    return d;
}
__device__ __forceinline__ float2 f2mul(float2 a, float2 b) {
    float2 d;
    asm("mul.rn.f32x2 %0, %1, %2;"
        : "=l"(*reinterpret_cast<unsigned long long*>(&d))
        : "l"(*reinterpret_cast<unsigned long long*>(&a)),
          "l"(*reinterpret_cast<unsigned long long*>(&b)));
    return d;
}
__device__ __forceinline__ void cpasync4(uint32_t dst, const float* src) {
    asm volatile("cp.async.ca.shared.global [%0], [%1], 4;"
                 :: "r"(dst), "l"(src) : "memory");
}
__device__ __forceinline__ void cp_commit() {
    asm volatile("cp.async.commit_group;" ::: "memory");
}
__device__ __forceinline__ void cp_wait0() {
    asm volatile("cp.async.wait_group 0;" ::: "memory");
}

// ---------------- merged tensor-product blocks (dual-output, R4) ----------------
template <int L, int O>
__device__ __forceinline__ void tp_diag(const float* __restrict__ x1,
                                        const float* __restrict__ x2,
                                        float* __restrict__ acc,
                                        float w0, float w1) {
    constexpr int D = 2 * L + 1;
    sfor<D>([&](auto I) {
        constexpr int i = decltype(I)::value;
        sfor<D>([&](auto J) {
            constexpr int j = decltype(J)::value;
            if constexpr (j >= i) {
                constexpr bool l0 = rowany2(CG<L, L, 4>, i, j, 9);
                constexpr bool l1 = rowany2(CG<L, L, 6>, i, j, 13);
                if constexpr (l0 || l1) {
                    if constexpr (i == j) {
                        float p = x1[O + i] * x2[O + i];
                        if constexpr (l0) {
                            float t = p * w0;
                            sfor<9>([&](auto K) {
                                constexpr int k = decltype(K)::value;
                                constexpr float cv = CG<L, L, 4>.v[i][i][k];
                                if constexpr (cv != 0.0f) acc[k] = __fmaf_rn(cv, t, acc[k]);
                            });
                        }
                        if constexpr (l1) {
                            float t = p * w1;
                            sfor<13>([&](auto K) {
                                constexpr int k = decltype(K)::value;
                                constexpr float cv = CG<L, L, 6>.v[i][i][k];
                                if constexpr (cv != 0.0f) acc[9 + k] = __fmaf_rn(cv, t, acc[9 + k]);
                            });
                        }
                    } else if constexpr (symk(CG<L, L, 4>, i, j, 9) && symk(CG<L, L, 6>, i, j, 13)) {
                        float s = __fmaf_rn(x1[O + j], x2[O + i], x1[O + i] * x2[O + j]);
                        if constexpr (l0) {
                            float t = s * w0;
                            sfor<9>([&](auto K) {
                                constexpr int k = decltype(K)::value;
                                constexpr float cv = CG<L, L, 4>.v[i][j][k];
                                if constexpr (cv != 0.0f) acc[k] = __fmaf_rn(cv, t, acc[k]);
                            });
                        }
                        if constexpr (l1) {
                            float t = s * w1;
                            sfor<13>([&](auto K) {
                                constexpr int k = decltype(K)::value;
                                constexpr float cv = CG<L, L, 6>.v[i][j][k];
                                if constexpr (cv != 0.0f) acc[9 + k] = __fmaf_rn(cv, t, acc[9 + k]);
                            });
                        }
                    } else {
                        float p1 = x1[O + i] * x2[O + j];
                        float p2 = x1[O + j] * x2[O + i];
                        if constexpr (l0) {
                            float t1 = p1 * w0, t2 = p2 * w0;
                            sfor<9>([&](auto K) {
                                constexpr int k = decltype(K)::value;
                                constexpr float c1 = CG<L, L, 4>.v[i][j][k];
                                constexpr float c2 = CG<L, L, 4>.v[j][i][k];
                                if constexpr (c1 != 0.0f) acc[k] = __fmaf_rn(c1, t1, acc[k]);
                                if constexpr (c2 != 0.0f) acc[k] = __fmaf_rn(c2, t2, acc[k]);
                            });
                        }
                        if constexpr (l1) {
                            float t1 = p1 * w1, t2 = p2 * w1;
                            sfor<13>([&](auto K) {
                                constexpr int k = decltype(K)::value;
                                constexpr float c1 = CG<L, L, 6>.v[i][j][k];
                                constexpr float c2 = CG<L, L, 6>.v[j][i][k];
                                if constexpr (c1 != 0.0f) acc[9 + k] = __fmaf_rn(c1, t1, acc[9 + k]);
                                if constexpr (c2 != 0.0f) acc[9 + k] = __fmaf_rn(c2, t2, acc[9 + k]);
                            });
                        }
                    }
                }
            }
        });
    });
}

__device__ __forceinline__ void tp_cross(const float* __restrict__ x1,
                                         const float* __restrict__ x2,
                                         float* __restrict__ acc,
                                         float wA0, float wA1, float wB0, float wB1) {
    sfor<9>([&](auto I) {
        constexpr int i = decltype(I)::value;
        sfor<13>([&](auto J) {
            constexpr int j = decltype(J)::value;
            constexpr bool a0 = rowany(CG<4, 6, 4>, i, j, 9);
            constexpr bool b0 = rowany(CG<6, 4, 4>, j, i, 9);
            constexpr bool a1 = rowany(CG<4, 6, 6>, i, j, 13);
            constexpr bool b1 = rowany(CG<6, 4, 6>, j, i, 13);
            if constexpr (a0 || b0 || a1 || b1) {
                float p1 = x1[i] * x2[9 + j];
                float p2 = x2[i] * x1[9 + j];
                if constexpr (a0 || b0) {
                    if constexpr (a0 && b0 && eqk(CG<4, 6, 4>, i, j, CG<6, 4, 4>, j, i, 9)) {
                        float u = __fmaf_rn(wB0, p2, p1 * wA0);
                        sfor<9>([&](auto K) {
                            constexpr int k = decltype(K)::value;
                            constexpr float cv = CG<4, 6, 4>.v[i][j][k];
                            if constexpr (cv != 0.0f) acc[k] = __fmaf_rn(cv, u, acc[k]);
                        });
                    } else {
                        if constexpr (a0) {
                            float t1 = p1 * wA0;
                            sfor<9>([&](auto K) {
                                constexpr int k = decltype(K)::value;
                                constexpr float cv = CG<4, 6, 4>.v[i][j][k];
                                if constexpr (cv != 0.0f) acc[k] = __fmaf_rn(cv, t1, acc[k]);
                            });
                        }
                        if constexpr (b0) {
                            float t2 = p2 * wB0;
                            sfor<9>([&](auto K) {
                                constexpr int k = decltype(K)::value;
                                constexpr float cv = CG<6, 4, 4>.v[j][i][k];
                                if constexpr (cv != 0.0f) acc[k] = __fmaf_rn(cv, t2, acc[k]);
                            });
                        }
                    }
                }
                if constexpr (a1 || b1) {
                    if constexpr (a1 && b1 && eqk(CG<4, 6, 6>, i, j, CG<6, 4, 6>, j, i, 13)) {
                        float u = __fmaf_rn(wB1, p2, p1 * wA1);
                        sfor<13>([&](auto K) {
                            constexpr int k = decltype(K)::value;
                            constexpr float cv = CG<4, 6, 6>.v[i][j][k];
                            if constexpr (cv != 0.0f) acc[9 + k] = __fmaf_rn(cv, u, acc[9 + k]);
                        });
                    } else {
                        if constexpr (a1) {
                            float t1 = p1 * wA1;
                            sfor<13>([&](auto K) {
                                constexpr int k = decltype(K)::value;
                                constexpr float cv = CG<4, 6, 6>.v[i][j][k];
                                if constexpr (cv != 0.0f) acc[9 + k] = __fmaf_rn(cv, t1, acc[9 + k]);
                            });
                        }
                        if constexpr (b1) {
                            float t2 = p2 * wB1;
                            sfor<13>([&](auto K) {
                                constexpr int k = decltype(K)::value;
                                constexpr float cv = CG<6, 4, 6>.v[j][i][k];
                                if constexpr (cv != 0.0f) acc[9 + k] = __fmaf_rn(cv, t2, acc[9 + k]);
                            });
                        }
                    }
                }
            }
        });
    });
}

// ---------------- kernel ----------------
constexpr int H = 768, W = 768;
constexpr int TX = 32, TY = 4;             // 128-thread tile
constexpr int NT = TX * TY;                // 128
constexpr int HTX = TX + 2, HTY = TY + 2;  // 34 x 6 haloed tile
constexpr int NPIX = HTX * HTY;            // 204
constexpr int NPAIR = 11;                  // 22 channels as 11 float2 pairs
constexpr int TILES_X = W / TX;            // 24
constexpr int NTILES = (W / TX) * (H / TY);  // 4608
constexpr int NCTA = 888;                  // 6/SM x 148: all resident from t=0

__global__ void __launch_bounds__(NT, 6) eq_spatial_tp_kernel(
    const float* __restrict__ f4, const float* __restrict__ f6,
    const float* __restrict__ sw, const float* __restrict__ wp,
    float* __restrict__ out4, float* __restrict__ out6) {
    // double-buffered channel-pair-major tiles (17952 B each)
    __shared__ float2 tileA[NPAIR * NPIX];
    __shared__ float2 tileB[NPAIR * NPIX];

    const int tid = threadIdx.x;
    const int tx = tid & 31, ty = tid >> 5;

    // async load of one haloed tile into buffer at smem addr sbase
    auto load_tile = [&](int tile, uint32_t sbase) {
        const int by = tile / TILES_X, bx = tile - by * TILES_X;
        const int gx0 = bx * TX - 1, gy0 = by * TY - 1;
#pragma unroll 5
        for (int idx = tid; idx < NPAIR * NPIX; idx += NT) {
            int p = idx / NPIX, pix = idx - p * NPIX;
            int r = pix / HTX, c = pix - r * HTX;
            int gy = gy0 + r; gy = gy < 0 ? 0 : (gy > H - 1 ? H - 1 : gy);
            int gx = gx0 + c; gx = gx < 0 ? 0 : (gx > W - 1 ? W - 1 : gx);
            int g = gy * W + gx;
            int ch = 2 * p;
            const float* s0 = (ch < 9) ? f4 + g * 9 + ch : f6 + g * 13 + (ch - 9);
            const float* s1 = (ch + 1 < 9) ? f4 + g * 9 + ch + 1 : f6 + g * 13 + (ch - 8);
            uint32_t d = sbase + (uint32_t)idx * 8u;
            cpasync4(d, s0);
            cpasync4(d + 4u, s1);
        }
        cp_commit();
    };

    const uint32_t sA = (uint32_t)__cvta_generic_to_shared(tileA);
    const uint32_t sB = (uint32_t)__cvta_generic_to_shared(tileB);

    // hoisted weights (persistent CTA: loaded once)
    float2 swp[9];
#pragma unroll
    for (int q = 0; q < 9; ++q) {
        float s = sw[q];
        swp[q] = make_float2(s, s);
    }
    float wcomb[8];
#pragma unroll
    for (int p = 0; p < 8; ++p) wcomb[p] = 0.5f * wp[p];  // ALPHA = 1/sqrt(4)

    int t = blockIdx.x;
    if (t >= NTILES) return;
    load_tile(t, sA);

    uint32_t scur = sA, snext = sB;
    const float2* bufs[2] = {tileA, tileB};
    int cur = 0;

    for (; t < NTILES; t += NCTA) {
        cp_wait0();
        __syncthreads();
        const int nt = t + NCTA;
        if (nt < NTILES) load_tile(nt, snext);

        const float2* buf = bufs[cur];

        // spatial average (packed f32x2)
        __align__(8) float x1[22], x2[22];
        float2* x1v = reinterpret_cast<float2*>(x1);
        float2* x2v = reinterpret_cast<float2*>(x2);
        {
            const int cpix = (ty + 1) * HTX + (tx + 1);
#pragma unroll
            for (int p = 0; p < NPAIR; ++p) {
                x1v[p] = buf[p * NPIX + cpix];
                x2v[p] = f2mul(swp[4], x1v[p]);
            }
        }
#pragma unroll
        for (int dy = 0; dy < 3; ++dy)
#pragma unroll
            for (int dx = 0; dx < 3; ++dx) {
                if (dy == 1 && dx == 1) continue;
                const int npix = (ty + dy) * HTX + (tx + dx);
                const float2 wq = swp[dy * 3 + dx];
#pragma unroll
                for (int p = 0; p < NPAIR; ++p)
                    x2v[p] = f2fma(wq, buf[p * NPIX + npix], x2v[p]);
            }

        float acc[22];
#pragma unroll
        for (int k = 0; k < 22; ++k) acc[k] = x1[k];  // residual folded

        tp_diag<4, 0>(x1, x2, acc, wcomb[0], wcomb[1]);
        tp_cross(x1, x2, acc, wcomb[2], wcomb[3], wcomb[4], wcomb[5]);
        tp_diag<6, 9>(x1, x2, acc, wcomb[6], wcomb[7]);

        // store
        const int by = t / TILES_X, bx = t - by * TILES_X;
        const int gy = by * TY + ty, gx = bx * TX + tx;
        const int g = gy * W + gx;
#pragma unroll
        for (int k = 0; k < 9; ++k) out4[g * 9 + k] = acc[k];
#pragma unroll
        for (int k = 0; k < 13; ++k) out6[g * 13 + k] = acc[9 + k];

        // swap buffers
        uint32_t stmp = scur; scur = snext; snext = stmp;
        cur ^= 1;
    }
}

extern "C" void kernel_launch(void* const* d_in, const int* in_sizes, int n_in,
                              void* d_out, int out_size) {
    const float* f4 = (const float*)d_in[0];
    const float* f6 = (const float*)d_in[1];
    const float* sw = (const float*)d_in[2];  // spatial_weights [3,3]
    const float* wp = (const float*)d_in[3];  // w_paths [8]
    float* out = (float*)d_out;
    const size_t N = (size_t)H * W;

    eq_spatial_tp_kernel<<<NCTA, NT>>>(f4, f6, sw, wp, out, out + N * 9);
}

// round 8
// speedup vs baseline: 4.4857x; 1.3329x over previous
#include <cuda_runtime.h>

// ============================================================================
// EquivariantSpatialConv: fused 3x3 replicate-pad depthwise spatial average
// + fully-connected CG tensor product (irreps 1x4e + 1x6e) + residual.
//
// R8: 64-thread CTAs (16x4 tile), __launch_bounds__(64, 14) -> 14 CTAs/SM
// (72 regs x 64 x 14 = 64512 just fits the RF). Same 28 warps/SM as R4 but
// 2x the independent phase machines; barriers are 2-warp-wide. TP stage is
// R4's single-pass merged blocks (CG immediates, symmetry-folded).
// ============================================================================

#define DEVHOST __host__ __device__

// ---------------- compile-time scalar math ----------------
DEVHOST constexpr double cfact(int n) {
    double r = 1.0;
    for (int i = 2; i <= n; ++i) r *= (double)i;
    return r;
}

DEVHOST constexpr double csqrt(double x) {
    if (x <= 0.0) return 0.0;
    double g = x > 1.0 ? x : 1.0;
    for (int it = 0; it < 48; ++it) g = 0.5 * (g + x / g);
    return g;
}

struct CD { double re, im; };
DEVHOST constexpr CD cmul(CD a, CD b) {
    return CD{a.re * b.re - a.im * b.im, a.re * b.im + a.im * b.re};
}
DEVHOST constexpr CD cconj(CD a) { return CD{a.re, -a.im}; }

DEVHOST constexpr double su2_cg(int j1, int j2, int j3, int m1, int m2, int m3) {
    if (m3 != m1 + m2) return 0.0;
    if (m1 < -j1 || m1 > j1 || m2 < -j2 || m2 > j2 || m3 < -j3 || m3 > j3) return 0.0;
    double pref0 = (2.0 * j3 + 1.0) * cfact(j1 + j2 - j3) * cfact(j1 - j2 + j3) *
                   cfact(-j1 + j2 + j3) / cfact(j1 + j2 + j3 + 1);
    double pref = csqrt(pref0 * cfact(j3 + m3) * cfact(j3 - m3) * cfact(j1 - m1) *
                        cfact(j1 + m1) * cfact(j2 - m2) * cfact(j2 + m2));
    int kmin = 0;
    if (-(j3 - j2 + m1) > kmin) kmin = -(j3 - j2 + m1);
    if (-(j3 - j1 - m2) > kmin) kmin = -(j3 - j1 - m2);
    int kmax = j1 + j2 - j3;
    if (j1 - m1 < kmax) kmax = j1 - m1;
    if (j2 + m2 < kmax) kmax = j2 + m2;
    double s = 0.0;
    for (int k = kmin; k <= kmax; ++k) {
        double d = cfact(k) * cfact(j1 + j2 - j3 - k) * cfact(j1 - m1 - k) *
                   cfact(j2 + m2 - k) * cfact(j3 - j2 + m1 + k) * cfact(j3 - j1 - m2 + k);
        s += ((k & 1) ? -1.0 : 1.0) / d;
    }
    return pref * s;
}

DEVHOST constexpr CD qent(int l, int r, int c) {
    constexpr double S2 = 0.70710678118654752440;
    int m = r - l;
    CD v{0.0, 0.0};
    if (m < 0) {
        if (c == l - m)      v = CD{S2, 0.0};
        else if (c == l + m) v = CD{0.0, -S2};
    } else if (m == 0) {
        if (c == l) v = CD{1.0, 0.0};
    } else {
        double sg = (m & 1) ? -1.0 : 1.0;
        if (c == l + m)      v = CD{sg * S2, 0.0};
        else if (c == l - m) v = CD{0.0, sg * S2};
    }
    int ph = l & 3;
    CD f = (ph == 0) ? CD{1, 0} : (ph == 1) ? CD{0, -1} : (ph == 2) ? CD{-1, 0} : CD{0, 1};
    return cmul(v, f);
}

DEVHOST constexpr double real_cg_entry(int l1, int l2, int l3, int a, int b, int c) {
    int d1 = a >= l1 ? a - l1 : l1 - a;
    int d2 = b >= l2 ? b - l2 : l2 - b;
    int d3 = c >= l3 ? c - l3 : l3 - c;
    CD sum{0.0, 0.0};
    int ni = d1 ? 2 : 1;
    int nk = d2 ? 2 : 1;
    for (int si = 0; si < ni; ++si) {
        int i = d1 ? (si ? l1 + d1 : l1 - d1) : l1;
        int m1 = i - l1;
        CD q1 = qent(l1, i, a);
        for (int sk = 0; sk < nk; ++sk) {
            int k = d2 ? (sk ? l2 + d2 : l2 - d2) : l2;
            int m2 = k - l2;
            int m3 = m1 + m2;
            if (m3 < -l3 || m3 > l3) continue;
            int am3 = m3 < 0 ? -m3 : m3;
            if (am3 != d3) continue;
            int n = l3 + m3;
            CD q2 = qent(l2, k, b);
            CD q3 = cconj(qent(l3, c, n));
            double C = su2_cg(l1, l2, l3, m1, m2, m3);
            CD t = cmul(cmul(q1, q2), q3);
            sum.re += t.re * C;
            sum.im += t.im * C;
        }
    }
    return sum.re;
}

template <int L1, int L2, int L3>
struct CGT {
    float v[2 * L1 + 1][2 * L2 + 1][2 * L3 + 1];
};

template <int L1, int L2, int L3>
DEVHOST constexpr CGT<L1, L2, L3> make_cg() {
    double tmp[2 * L1 + 1][2 * L2 + 1][2 * L3 + 1] = {};
    double ss = 0.0;
    for (int a = 0; a < 2 * L1 + 1; ++a)
        for (int b = 0; b < 2 * L2 + 1; ++b)
            for (int c = 0; c < 2 * L3 + 1; ++c) {
                double e = real_cg_entry(L1, L2, L3, a, b, c);
                tmp[a][b][c] = e;
                ss += e * e;
            }
    double inv = 1.0 / csqrt(ss);
    CGT<L1, L2, L3> r{};
    for (int a = 0; a < 2 * L1 + 1; ++a)
        for (int b = 0; b < 2 * L2 + 1; ++b)
            for (int c = 0; c < 2 * L3 + 1; ++c)
                r.v[a][b][c] = (float)(tmp[a][b][c] * inv);
    return r;
}

// Namespace-scope constexpr CG tensors (static storage: usable in constant
// expressions from any lambda depth inside function templates).
template <int L1, int L2, int L3>
inline constexpr CGT<L1, L2, L3> CG = make_cg<L1, L2, L3>();

// ---------------- compile-time unrolling helpers ----------------
template <int V> struct IC { static constexpr int value = V; };

template <int N, int I = 0, class F>
__device__ __forceinline__ void sfor(F&& f) {
    if constexpr (I < N) {
        f(IC<I>{});
        sfor<N, I + 1>(static_cast<F&&>(f));
    }
}

template <class T>
DEVHOST constexpr bool rowany(const T& t, int a, int b, int dk) {
    for (int k = 0; k < dk; ++k)
        if (t.v[a][b][k] != 0.0f) return true;
    return false;
}
template <class T>
DEVHOST constexpr bool rowany2(const T& t, int a, int b, int dk) {
    for (int k = 0; k < dk; ++k)
        if (t.v[a][b][k] != 0.0f || t.v[b][a][k] != 0.0f) return true;
    return false;
}
template <class T>
DEVHOST constexpr bool symk(const T& t, int a, int b, int dk) {
    for (int k = 0; k < dk; ++k)
        if (t.v[a][b][k] != t.v[b][a][k]) return false;
    return true;
}
template <class TA, class TB>
DEVHOST constexpr bool eqk(const TA& A, int i, int j, const TB& B, int bi, int bj, int dk) {
    for (int k = 0; k < dk; ++k)
        if (A.v[i][j][k] != B.v[bi][bj][k]) return false;
    return true;
}

// ---------------- packed f32x2 helpers ----------------
__device__ __forceinline__ float2 f2fma(float2 a, float2 b, float2 c) {
    float2 d;
    asm("fma.rn.f32x2 %0, %1, %2, %3;"
        : "=l"(*reinterpret_cast<unsigned long long*>(&d))
        : "l"(*reinterpret_cast<unsigned long long*>(&a)),
          "l"(*reinterpret_cast<unsigned long long*>(&b)),
          "l"(*reinterpret_cast<unsigned long long*>(&c)));
    return d;
}
__device__ __forceinline__ float2 f2mul(float2 a, float2 b) {
    float2 d;
    asm("mul.rn.f32x2 %0, %1, %2;"
        : "=l"(*reinterpret_cast<unsigned long long*>(&d))
        : "l"(*reinterpret_cast<unsigned long long*>(&a)),
          "l"(*reinterpret_cast<unsigned long long*>(&b)));
    return d;
}

// ---------------- merged tensor-product blocks (dual-output) ----------------
template <int L, int O>
__device__ __forceinline__ void tp_diag(const float* __restrict__ x1,
                                        const float* __restrict__ x2,
                                        float* __restrict__ acc,
                                        float w0, float w1) {
    constexpr int D = 2 * L + 1;
    sfor<D>([&](auto I) {
        constexpr int i = decltype(I)::value;
        sfor<D>([&](auto J) {
            constexpr int j = decltype(J)::value;
            if constexpr (j >= i) {
                constexpr bool l0 = rowany2(CG<L, L, 4>, i, j, 9);
                constexpr bool l1 = rowany2(CG<L, L, 6>, i, j, 13);
                if constexpr (l0 || l1) {
                    if constexpr (i == j) {
                        float p = x1[O + i] * x2[O + i];
                        if constexpr (l0) {
                            float t = p * w0;
                            sfor<9>([&](auto K) {
                                constexpr int k = decltype(K)::value;
                                constexpr float cv = CG<L, L, 4>.v[i][i][k];
                                if constexpr (cv != 0.0f) acc[k] = __fmaf_rn(cv, t, acc[k]);
                            });
                        }
                        if constexpr (l1) {
                            float t = p * w1;
                            sfor<13>([&](auto K) {
                                constexpr int k = decltype(K)::value;
                                constexpr float cv = CG<L, L, 6>.v[i][i][k];
                                if constexpr (cv != 0.0f) acc[9 + k] = __fmaf_rn(cv, t, acc[9 + k]);
                            });
                        }
                    } else if constexpr (symk(CG<L, L, 4>, i, j, 9) && symk(CG<L, L, 6>, i, j, 13)) {
                        float s = __fmaf_rn(x1[O + j], x2[O + i], x1[O + i] * x2[O + j]);
                        if constexpr (l0) {
                            float t = s * w0;
                            sfor<9>([&](auto K) {
                                constexpr int k = decltype(K)::value;
                                constexpr float cv = CG<L, L, 4>.v[i][j][k];
                                if constexpr (cv != 0.0f) acc[k] = __fmaf_rn(cv, t, acc[k]);
                            });
                        }
                        if constexpr (l1) {
                            float t = s * w1;
                            sfor<13>([&](auto K) {
                                constexpr int k = decltype(K)::value;
                                constexpr float cv = CG<L, L, 6>.v[i][j][k];
                                if constexpr (cv != 0.0f) acc[9 + k] = __fmaf_rn(cv, t, acc[9 + k]);
                            });
                        }
                    } else {
                        float p1 = x1[O + i] * x2[O + j];
                        float p2 = x1[O + j] * x2[O + i];
                        if constexpr (l0) {
                            float t1 = p1 * w0, t2 = p2 * w0;
                            sfor<9>([&](auto K) {
                                constexpr int k = decltype(K)::value;
                                constexpr float c1 = CG<L, L, 4>.v[i][j][k];
                                constexpr float c2 = CG<L, L, 4>.v[j][i][k];
                                if constexpr (c1 != 0.0f) acc[k] = __fmaf_rn(c1, t1, acc[k]);
                                if constexpr (c2 != 0.0f) acc[k] = __fmaf_rn(c2, t2, acc[k]);
                            });
                        }
                        if constexpr (l1) {
                            float t1 = p1 * w1, t2 = p2 * w1;
                            sfor<13>([&](auto K) {
                                constexpr int k = decltype(K)::value;
                                constexpr float c1 = CG<L, L, 6>.v[i][j][k];
                                constexpr float c2 = CG<L, L, 6>.v[j][i][k];
                                if constexpr (c1 != 0.0f) acc[9 + k] = __fmaf_rn(c1, t1, acc[9 + k]);
                                if constexpr (c2 != 0.0f) acc[9 + k] = __fmaf_rn(c2, t2, acc[9 + k]);
                            });
                        }
                    }
                }
            }
        });
    });
}

__device__ __forceinline__ void tp_cross(const float* __restrict__ x1,
                                         const float* __restrict__ x2,
                                         float* __restrict__ acc,
                                         float wA0, float wA1, float wB0, float wB1) {
    sfor<9>([&](auto I) {
        constexpr int i = decltype(I)::value;
        sfor<13>([&](auto J) {
            constexpr int j = decltype(J)::value;
            constexpr bool a0 = rowany(CG<4, 6, 4>, i, j, 9);
            constexpr bool b0 = rowany(CG<6, 4, 4>, j, i, 9);
            constexpr bool a1 = rowany(CG<4, 6, 6>, i, j, 13);
            constexpr bool b1 = rowany(CG<6, 4, 6>, j, i, 13);
            if constexpr (a0 || b0 || a1 || b1) {
                float p1 = x1[i] * x2[9 + j];
                float p2 = x2[i] * x1[9 + j];
                if constexpr (a0 || b0) {
                    if constexpr (a0 && b0 && eqk(CG<4, 6, 4>, i, j, CG<6, 4, 4>, j, i, 9)) {
                        float u = __fmaf_rn(wB0, p2, p1 * wA0);
                        sfor<9>([&](auto K) {
                            constexpr int k = decltype(K)::value;
                            constexpr float cv = CG<4, 6, 4>.v[i][j][k];
                            if constexpr (cv != 0.0f) acc[k] = __fmaf_rn(cv, u, acc[k]);
                        });
                    } else {
                        if constexpr (a0) {
                            float t1 = p1 * wA0;
                            sfor<9>([&](auto K) {
                                constexpr int k = decltype(K)::value;
                                constexpr float cv = CG<4, 6, 4>.v[i][j][k];
                                if constexpr (cv != 0.0f) acc[k] = __fmaf_rn(cv, t1, acc[k]);
                            });
                        }
                        if constexpr (b0) {
                            float t2 = p2 * wB0;
                            sfor<9>([&](auto K) {
                                constexpr int k = decltype(K)::value;
                                constexpr float cv = CG<6, 4, 4>.v[j][i][k];
                                if constexpr (cv != 0.0f) acc[k] = __fmaf_rn(cv, t2, acc[k]);
                            });
                        }
                    }
                }
                if constexpr (a1 || b1) {
                    if constexpr (a1 && b1 && eqk(CG<4, 6, 6>, i, j, CG<6, 4, 6>, j, i, 13)) {
                        float u = __fmaf_rn(wB1, p2, p1 * wA1);
                        sfor<13>([&](auto K) {
                            constexpr int k = decltype(K)::value;
                            constexpr float cv = CG<4, 6, 6>.v[i][j][k];
                            if constexpr (cv != 0.0f) acc[9 + k] = __fmaf_rn(cv, u, acc[9 + k]);
                        });
                    } else {
                        if constexpr (a1) {
                            float t1 = p1 * wA1;
                            sfor<13>([&](auto K) {
                                constexpr int k = decltype(K)::value;
                                constexpr float cv = CG<4, 6, 6>.v[i][j][k];
                                if constexpr (cv != 0.0f) acc[9 + k] = __fmaf_rn(cv, t1, acc[9 + k]);
                            });
                        }
                        if constexpr (b1) {
                            float t2 = p2 * wB1;
                            sfor<13>([&](auto K) {
                                constexpr int k = decltype(K)::value;
                                constexpr float cv = CG<6, 4, 6>.v[j][i][k];
                                if constexpr (cv != 0.0f) acc[9 + k] = __fmaf_rn(cv, t2, acc[9 + k]);
                            });
                        }
                    }
                }
            }
        });
    });
}

// ---------------- kernel ----------------
constexpr int H = 768, W = 768;
constexpr int TX = 16, TY = 4;             // 64-thread tile
constexpr int NT = TX * TY;                // 64
constexpr int HTX = TX + 2, HTY = TY + 2;  // 18 x 6 haloed tile
constexpr int NPIX = HTX * HTY;            // 108
constexpr int NPAIR = 11;                  // 22 channels as 11 float2 pairs

__global__ void __launch_bounds__(NT, 14) eq_spatial_tp_kernel(
    const float* __restrict__ f4, const float* __restrict__ f6,
    const float* __restrict__ sw, const float* __restrict__ wp,
    float* __restrict__ out4, float* __restrict__ out6) {
    // channel-pair-major: tile[p][pix]; lane-consecutive pix -> conflict-free LDS.64
    __shared__ float2 tile[NPAIR * NPIX];  // 11968 B; x14 CTAs = 167 KB/SM

    const int tid = threadIdx.x;
    const int bx = blockIdx.x, by = blockIdx.y;
    const int gx0 = bx * TX - 1, gy0 = by * TY - 1;

    // hoist weight loads so their latency overlaps the tile load
    float2 swp[9];
#pragma unroll
    for (int q = 0; q < 9; ++q) {
        float s = sw[q];
        swp[q] = make_float2(s, s);
    }
    float wcomb[8];
#pragma unroll
    for (int p = 0; p < 8; ++p) wcomb[p] = 0.5f * wp[p];  // ALPHA = 1/sqrt(4)

    // Cooperative haloed-tile load with replicate clamping.
#pragma unroll 4
    for (int idx = tid; idx < NPAIR * NPIX; idx += NT) {
        int p = idx / NPIX, pix = idx - p * NPIX;
        int r = pix / HTX, c = pix - r * HTX;
        int gy = gy0 + r; gy = gy < 0 ? 0 : (gy > H - 1 ? H - 1 : gy);
        int gx = gx0 + c; gx = gx < 0 ? 0 : (gx > W - 1 ? W - 1 : gx);
        int g = gy * W + gx;
        int ch = 2 * p;
        float v0 = (ch < 9) ? f4[g * 9 + ch] : f6[g * 13 + (ch - 9)];
        float v1 = (ch + 1 < 9) ? f4[g * 9 + ch + 1] : f6[g * 13 + (ch + 1 - 9)];
        tile[idx] = make_float2(v0, v1);
    }
    __syncthreads();

    const int tx = tid & (TX - 1), ty = tid / TX;

    // x1 = center features; x2 = weighted 3x3 neighbor average (packed f32x2)
    __align__(8) float x1[22], x2[22];
    float2* x1v = reinterpret_cast<float2*>(x1);
    float2* x2v = reinterpret_cast<float2*>(x2);
    {
        const int cpix = (ty + 1) * HTX + (tx + 1);
#pragma unroll
        for (int p = 0; p < NPAIR; ++p) {
            x1v[p] = tile[p * NPIX + cpix];
            x2v[p] = f2mul(swp[4], x1v[p]);
        }
    }
#pragma unroll
    for (int dy = 0; dy < 3; ++dy)
#pragma unroll
        for (int dx = 0; dx < 3; ++dx) {
            if (dy == 1 && dx == 1) continue;
            const int npix = (ty + dy) * HTX + (tx + dx);
            const float2 wq = swp[dy * 3 + dx];
#pragma unroll
            for (int p = 0; p < NPAIR; ++p)
                x2v[p] = f2fma(wq, tile[p * NPIX + npix], x2v[p]);
        }

    float acc[22];
#pragma unroll
    for (int k = 0; k < 22; ++k) acc[k] = x1[k];  // residual folded into init

    // merged path blocks: p = a*4 + b*2 + c
    tp_diag<4, 0>(x1, x2, acc, wcomb[0], wcomb[1]);
    tp_cross(x1, x2, acc, wcomb[2], wcomb[3], wcomb[4], wcomb[5]);
    tp_diag<6, 9>(x1, x2, acc, wcomb[6], wcomb[7]);

    // store (output layout: flat [N*9] then [N*13])
    const int gy = by * TY + ty, gx = bx * TX + tx;
    const int g = gy * W + gx;
#pragma unroll
    for (int k = 0; k < 9; ++k) out4[g * 9 + k] = acc[k];
#pragma unroll
    for (int k = 0; k < 13; ++k) out6[g * 13 + k] = acc[9 + k];
}

extern "C" void kernel_launch(void* const* d_in, const int* in_sizes, int n_in,
                              void* d_out, int out_size) {
    const float* f4 = (const float*)d_in[0];
    const float* f6 = (const float*)d_in[1];
    const float* sw = (const float*)d_in[2];  // spatial_weights [3,3]
    const float* wp = (const float*)d_in[3];  // w_paths [8]
    float* out = (float*)d_out;
    const size_t N = (size_t)H * W;

    dim3 grid(W / TX, H / TY);  // 48 x 192
    eq_spatial_tp_kernel<<<grid, NT>>>(f4, f6, sw, wp, out, out + N * 9);
}

// round 9
// speedup vs baseline: 5.9317x; 1.3224x over previous
#include <cuda_runtime.h>

// ============================================================================
// EquivariantSpatialConv: fused 3x3 replicate-pad depthwise spatial average
// + fully-connected CG tensor product (irreps 1x4e + 1x6e) + residual.
//
// R9: R4 shape (128-thr CTAs, 7/SM) + streamlined I/O:
//   - pixel-outer tile load: per-pixel base pointers, 22 compile-time-offset
//     LDG (no runtime f4/f6 predication, no per-element div/mod), STS.128
//   - float4-group smem layout: spatial LDS count 99 -> 54 (conflict-free)
// TP stage unchanged (CG immediates, symmetry-folded) -> bit-identical math.
// ============================================================================

#define DEVHOST __host__ __device__

// ---------------- compile-time scalar math ----------------
DEVHOST constexpr double cfact(int n) {
    double r = 1.0;
    for (int i = 2; i <= n; ++i) r *= (double)i;
    return r;
}

DEVHOST constexpr double csqrt(double x) {
    if (x <= 0.0) return 0.0;
    double g = x > 1.0 ? x : 1.0;
    for (int it = 0; it < 48; ++it) g = 0.5 * (g + x / g);
    return g;
}

struct CD { double re, im; };
DEVHOST constexpr CD cmul(CD a, CD b) {
    return CD{a.re * b.re - a.im * b.im, a.re * b.im + a.im * b.re};
}
DEVHOST constexpr CD cconj(CD a) { return CD{a.re, -a.im}; }

DEVHOST constexpr double su2_cg(int j1, int j2, int j3, int m1, int m2, int m3) {
    if (m3 != m1 + m2) return 0.0;
    if (m1 < -j1 || m1 > j1 || m2 < -j2 || m2 > j2 || m3 < -j3 || m3 > j3) return 0.0;
    double pref0 = (2.0 * j3 + 1.0) * cfact(j1 + j2 - j3) * cfact(j1 - j2 + j3) *
                   cfact(-j1 + j2 + j3) / cfact(j1 + j2 + j3 + 1);
    double pref = csqrt(pref0 * cfact(j3 + m3) * cfact(j3 - m3) * cfact(j1 - m1) *
                        cfact(j1 + m1) * cfact(j2 - m2) * cfact(j2 + m2));
    int kmin = 0;
    if (-(j3 - j2 + m1) > kmin) kmin = -(j3 - j2 + m1);
    if (-(j3 - j1 - m2) > kmin) kmin = -(j3 - j1 - m2);
    int kmax = j1 + j2 - j3;
    if (j1 - m1 < kmax) kmax = j1 - m1;
    if (j2 + m2 < kmax) kmax = j2 + m2;
    double s = 0.0;
    for (int k = kmin; k <= kmax; ++k) {
        double d = cfact(k) * cfact(j1 + j2 - j3 - k) * cfact(j1 - m1 - k) *
                   cfact(j2 + m2 - k) * cfact(j3 - j2 + m1 + k) * cfact(j3 - j1 - m2 + k);
        s += ((k & 1) ? -1.0 : 1.0) / d;
    }
    return pref * s;
}

DEVHOST constexpr CD qent(int l, int r, int c) {
    constexpr double S2 = 0.70710678118654752440;
    int m = r - l;
    CD v{0.0, 0.0};
    if (m < 0) {
        if (c == l - m)      v = CD{S2, 0.0};
        else if (c == l + m) v = CD{0.0, -S2};
    } else if (m == 0) {
        if (c == l) v = CD{1.0, 0.0};
    } else {
        double sg = (m & 1) ? -1.0 : 1.0;
        if (c == l + m)      v = CD{sg * S2, 0.0};
        else if (c == l - m) v = CD{0.0, sg * S2};
    }
    int ph = l & 3;
    CD f = (ph == 0) ? CD{1, 0} : (ph == 1) ? CD{0, -1} : (ph == 2) ? CD{-1, 0} : CD{0, 1};
    return cmul(v, f);
}

DEVHOST constexpr double real_cg_entry(int l1, int l2, int l3, int a, int b, int c) {
    int d1 = a >= l1 ? a - l1 : l1 - a;
    int d2 = b >= l2 ? b - l2 : l2 - b;
    int d3 = c >= l3 ? c - l3 : l3 - c;
    CD sum{0.0, 0.0};
    int ni = d1 ? 2 : 1;
    int nk = d2 ? 2 : 1;
    for (int si = 0; si < ni; ++si) {
        int i = d1 ? (si ? l1 + d1 : l1 - d1) : l1;
        int m1 = i - l1;
        CD q1 = qent(l1, i, a);
        for (int sk = 0; sk < nk; ++sk) {
            int k = d2 ? (sk ? l2 + d2 : l2 - d2) : l2;
            int m2 = k - l2;
            int m3 = m1 + m2;
            if (m3 < -l3 || m3 > l3) continue;
            int am3 = m3 < 0 ? -m3 : m3;
            if (am3 != d3) continue;
            int n = l3 + m3;
            CD q2 = qent(l2, k, b);
            CD q3 = cconj(qent(l3, c, n));
            double C = su2_cg(l1, l2, l3, m1, m2, m3);
            CD t = cmul(cmul(q1, q2), q3);
            sum.re += t.re * C;
            sum.im += t.im * C;
        }
    }
    return sum.re;
}

template <int L1, int L2, int L3>
struct CGT {
    float v[2 * L1 + 1][2 * L2 + 1][2 * L3 + 1];
};

template <int L1, int L2, int L3>
DEVHOST constexpr CGT<L1, L2, L3> make_cg() {
    double tmp[2 * L1 + 1][2 * L2 + 1][2 * L3 + 1] = {};
    double ss = 0.0;
    for (int a = 0; a < 2 * L1 + 1; ++a)
        for (int b = 0; b < 2 * L2 + 1; ++b)
            for (int c = 0; c < 2 * L3 + 1; ++c) {
                double e = real_cg_entry(L1, L2, L3, a, b, c);
                tmp[a][b][c] = e;
                ss += e * e;
            }
    double inv = 1.0 / csqrt(ss);
    CGT<L1, L2, L3> r{};
    for (int a = 0; a < 2 * L1 + 1; ++a)
        for (int b = 0; b < 2 * L2 + 1; ++b)
            for (int c = 0; c < 2 * L3 + 1; ++c)
                r.v[a][b][c] = (float)(tmp[a][b][c] * inv);
    return r;
}

// Namespace-scope constexpr CG tensors (static storage: usable in constant
// expressions from any lambda depth inside function templates).
template <int L1, int L2, int L3>
inline constexpr CGT<L1, L2, L3> CG = make_cg<L1, L2, L3>();

// ---------------- compile-time unrolling helpers ----------------
template <int V> struct IC { static constexpr int value = V; };

template <int N, int I = 0, class F>
__device__ __forceinline__ void sfor(F&& f) {
    if constexpr (I < N) {
        f(IC<I>{});
        sfor<N, I + 1>(static_cast<F&&>(f));
    }
}

template <class T>
DEVHOST constexpr bool rowany(const T& t, int a, int b, int dk) {
    for (int k = 0; k < dk; ++k)
        if (t.v[a][b][k] != 0.0f) return true;
    return false;
}
template <class T>
DEVHOST constexpr bool rowany2(const T& t, int a, int b, int dk) {
    for (int k = 0; k < dk; ++k)
        if (t.v[a][b][k] != 0.0f || t.v[b][a][k] != 0.0f) return true;
    return false;
}
template <class T>
DEVHOST constexpr bool symk(const T& t, int a, int b, int dk) {
    for (int k = 0; k < dk; ++k)
        if (t.v[a][b][k] != t.v[b][a][k]) return false;
    return true;
}
template <class TA, class TB>
DEVHOST constexpr bool eqk(const TA& A, int i, int j, const TB& B, int bi, int bj, int dk) {
    for (int k = 0; k < dk; ++k)
        if (A.v[i][j][k] != B.v[bi][bj][k]) return false;
    return true;
}

// ---------------- packed f32x2 helpers ----------------
__device__ __forceinline__ float2 f2fma(float2 a, float2 b, float2 c) {
    float2 d;
    asm("fma.rn.f32x2 %0, %1, %2, %3;"
        : "=l"(*reinterpret_cast<unsigned long long*>(&d))
        : "l"(*reinterpret_cast<unsigned long long*>(&a)),
          "l"(*reinterpret_cast<unsigned long long*>(&b)),
          "l"(*reinterpret_cast<unsigned long long*>(&c)));
    return d;
}
__device__ __forceinline__ float2 f2mul(float2 a, float2 b) {
    float2 d;
    asm("mul.rn.f32x2 %0, %1, %2;"
        : "=l"(*reinterpret_cast<unsigned long long*>(&d))
        : "l"(*reinterpret_cast<unsigned long long*>(&a)),
          "l"(*reinterpret_cast<unsigned long long*>(&b)));
    return d;
}

// ---------------- merged tensor-product blocks (dual-output) ----------------
template <int L, int O>
__device__ __forceinline__ void tp_diag(const float* __restrict__ x1,
                                        const float* __restrict__ x2,
                                        float* __restrict__ acc,
                                        float w0, float w1) {
    constexpr int D = 2 * L + 1;
    sfor<D>([&](auto I) {
        constexpr int i = decltype(I)::value;
        sfor<D>([&](auto J) {
            constexpr int j = decltype(J)::value;
            if constexpr (j >= i) {
                constexpr bool l0 = rowany2(CG<L, L, 4>, i, j, 9);
                constexpr bool l1 = rowany2(CG<L, L, 6>, i, j, 13);
                if constexpr (l0 || l1) {
                    if constexpr (i == j) {
                        float p = x1[O + i] * x2[O + i];
                        if constexpr (l0) {
                            float t = p * w0;
                            sfor<9>([&](auto K) {
                                constexpr int k = decltype(K)::value;
                                constexpr float cv = CG<L, L, 4>.v[i][i][k];
                                if constexpr (cv != 0.0f) acc[k] = __fmaf_rn(cv, t, acc[k]);
                            });
                        }
                        if constexpr (l1) {
                            float t = p * w1;
                            sfor<13>([&](auto K) {
                                constexpr int k = decltype(K)::value;
                                constexpr float cv = CG<L, L, 6>.v[i][i][k];
                                if constexpr (cv != 0.0f) acc[9 + k] = __fmaf_rn(cv, t, acc[9 + k]);
                            });
                        }
                    } else if constexpr (symk(CG<L, L, 4>, i, j, 9) && symk(CG<L, L, 6>, i, j, 13)) {
                        float s = __fmaf_rn(x1[O + j], x2[O + i], x1[O + i] * x2[O + j]);
                        if constexpr (l0) {
                            float t = s * w0;
                            sfor<9>([&](auto K) {
                                constexpr int k = decltype(K)::value;
                                constexpr float cv = CG<L, L, 4>.v[i][j][k];
                                if constexpr (cv != 0.0f) acc[k] = __fmaf_rn(cv, t, acc[k]);
                            });
                        }
                        if constexpr (l1) {
                            float t = s * w1;
                            sfor<13>([&](auto K) {
                                constexpr int k = decltype(K)::value;
                                constexpr float cv = CG<L, L, 6>.v[i][j][k];
                                if constexpr (cv != 0.0f) acc[9 + k] = __fmaf_rn(cv, t, acc[9 + k]);
                            });
                        }
                    } else {
                        float p1 = x1[O + i] * x2[O + j];
                        float p2 = x1[O + j] * x2[O + i];
                        if constexpr (l0) {
                            float t1 = p1 * w0, t2 = p2 * w0;
                            sfor<9>([&](auto K) {
                                constexpr int k = decltype(K)::value;
                                constexpr float c1 = CG<L, L, 4>.v[i][j][k];
                                constexpr float c2 = CG<L, L, 4>.v[j][i][k];
                                if constexpr (c1 != 0.0f) acc[k] = __fmaf_rn(c1, t1, acc[k]);
                                if constexpr (c2 != 0.0f) acc[k] = __fmaf_rn(c2, t2, acc[k]);
                            });
                        }
                        if constexpr (l1) {
                            float t1 = p1 * w1, t2 = p2 * w1;
                            sfor<13>([&](auto K) {
                                constexpr int k = decltype(K)::value;
                                constexpr float c1 = CG<L, L, 6>.v[i][j][k];
                                constexpr float c2 = CG<L, L, 6>.v[j][i][k];
                                if constexpr (c1 != 0.0f) acc[9 + k] = __fmaf_rn(c1, t1, acc[9 + k]);
                                if constexpr (c2 != 0.0f) acc[9 + k] = __fmaf_rn(c2, t2, acc[9 + k]);
                            });
                        }
                    }
                }
            }
        });
    });
}

__device__ __forceinline__ void tp_cross(const float* __restrict__ x1,
                                         const float* __restrict__ x2,
                                         float* __restrict__ acc,
                                         float wA0, float wA1, float wB0, float wB1) {
    sfor<9>([&](auto I) {
        constexpr int i = decltype(I)::value;
        sfor<13>([&](auto J) {
            constexpr int j = decltype(J)::value;
            constexpr bool a0 = rowany(CG<4, 6, 4>, i, j, 9);
            constexpr bool b0 = rowany(CG<6, 4, 4>, j, i, 9);
            constexpr bool a1 = rowany(CG<4, 6, 6>, i, j, 13);
            constexpr bool b1 = rowany(CG<6, 4, 6>, j, i, 13);
            if constexpr (a0 || b0 || a1 || b1) {
                float p1 = x1[i] * x2[9 + j];
                float p2 = x2[i] * x1[9 + j];
                if constexpr (a0 || b0) {
                    if constexpr (a0 && b0 && eqk(CG<4, 6, 4>, i, j, CG<6, 4, 4>, j, i, 9)) {
                        float u = __fmaf_rn(wB0, p2, p1 * wA0);
                        sfor<9>([&](auto K) {
                            constexpr int k = decltype(K)::value;
                            constexpr float cv = CG<4, 6, 4>.v[i][j][k];
                            if constexpr (cv != 0.0f) acc[k] = __fmaf_rn(cv, u, acc[k]);
                        });
                    } else {
                        if constexpr (a0) {
                            float t1 = p1 * wA0;
                            sfor<9>([&](auto K) {
                                constexpr int k = decltype(K)::value;
                                constexpr float cv = CG<4, 6, 4>.v[i][j][k];
                                if constexpr (cv != 0.0f) acc[k] = __fmaf_rn(cv, t1, acc[k]);
                            });
                        }
                        if constexpr (b0) {
                            float t2 = p2 * wB0;
                            sfor<9>([&](auto K) {
                                constexpr int k = decltype(K)::value;
                                constexpr float cv = CG<6, 4, 4>.v[j][i][k];
                                if constexpr (cv != 0.0f) acc[k] = __fmaf_rn(cv, t2, acc[k]);
                            });
                        }
                    }
                }
                if constexpr (a1 || b1) {
                    if constexpr (a1 && b1 && eqk(CG<4, 6, 6>, i, j, CG<6, 4, 6>, j, i, 13)) {
                        float u = __fmaf_rn(wB1, p2, p1 * wA1);
                        sfor<13>([&](auto K) {
                            constexpr int k = decltype(K)::value;
                            constexpr float cv = CG<4, 6, 6>.v[i][j][k];
                            if constexpr (cv != 0.0f) acc[9 + k] = __fmaf_rn(cv, u, acc[9 + k]);
                        });
                    } else {
                        if constexpr (a1) {
                            float t1 = p1 * wA1;
                            sfor<13>([&](auto K) {
                                constexpr int k = decltype(K)::value;
                                constexpr float cv = CG<4, 6, 6>.v[i][j][k];
                                if constexpr (cv != 0.0f) acc[9 + k] = __fmaf_rn(cv, t1, acc[9 + k]);
                            });
                        }
                        if constexpr (b1) {
                            float t2 = p2 * wB1;
                            sfor<13>([&](auto K) {
                                constexpr int k = decltype(K)::value;
                                constexpr float cv = CG<6, 4, 6>.v[j][i][k];
                                if constexpr (cv != 0.0f) acc[9 + k] = __fmaf_rn(cv, t2, acc[9 + k]);
                            });
                        }
                    }
                }
            }
        });
    });
}

// ---------------- kernel ----------------
constexpr int H = 768, W = 768;
constexpr int TX = 32, TY = 4;             // 128-thread tile
constexpr int NT = TX * TY;                // 128
constexpr int HTX = TX + 2, HTY = TY + 2;  // 34 x 6 haloed tile
constexpr int NPIX = HTX * HTY;            // 204

__global__ void __launch_bounds__(NT, 7) eq_spatial_tp_kernel(
    const float* __restrict__ f4, const float* __restrict__ f6,
    const float* __restrict__ sw, const float* __restrict__ wp,
    float* __restrict__ out4, float* __restrict__ out6) {
    // float4-group, pixel-major smem: groups 0-4 hold ch 4g..4g+3, group 5 ch 20-21.
    __shared__ float4 tile4[5][NPIX];   // 16320 B
    __shared__ float2 tile5[NPIX];      // 1632 B -> 17952 B total, 7 CTAs = 126 KB

    const int tid = threadIdx.x;
    const int bx = blockIdx.x, by = blockIdx.y;
    const int gx0 = bx * TX - 1, gy0 = by * TY - 1;

    // hoist weight loads so their latency overlaps the tile load
    float2 swp[9];
#pragma unroll
    for (int q = 0; q < 9; ++q) {
        float s = sw[q];
        swp[q] = make_float2(s, s);
    }
    float wcomb[8];
#pragma unroll
    for (int p = 0; p < 8; ++p) wcomb[p] = 0.5f * wp[p];  // ALPHA = 1/sqrt(4)

    // ---- pixel-outer haloed-tile load (2 pixels/thread, compile-time offsets) ----
#pragma unroll
    for (int pix = tid; pix < NPIX; pix += NT) {
        int r = pix / HTX, c = pix - r * HTX;
        int gy = gy0 + r; gy = gy < 0 ? 0 : (gy > H - 1 ? H - 1 : gy);
        int gx = gx0 + c; gx = gx < 0 ? 0 : (gx > W - 1 ? W - 1 : gx);
        int g = gy * W + gx;
        const float* p4 = f4 + g * 9;
        const float* p6 = f6 + g * 13;
        float v[22];
#pragma unroll
        for (int ch = 0; ch < 9; ++ch) v[ch] = p4[ch];
#pragma unroll
        for (int ch = 0; ch < 13; ++ch) v[9 + ch] = p6[ch];
#pragma unroll
        for (int gg = 0; gg < 5; ++gg)
            tile4[gg][pix] = make_float4(v[4 * gg], v[4 * gg + 1], v[4 * gg + 2], v[4 * gg + 3]);
        tile5[pix] = make_float2(v[20], v[21]);
    }
    __syncthreads();

    const int tx = tid & 31, ty = tid >> 5;

    // x1 = center features; x2 = weighted 3x3 neighbor average (packed f32x2)
    __align__(16) float x1[22];
    __align__(8) float x2[22];
    float2* x1v = reinterpret_cast<float2*>(x1);
    float2* x2v = reinterpret_cast<float2*>(x2);
    {
        const int cpix = (ty + 1) * HTX + (tx + 1);
#pragma unroll
        for (int gg = 0; gg < 5; ++gg) {
            float4 t = tile4[gg][cpix];
            x1v[2 * gg] = make_float2(t.x, t.y);
            x1v[2 * gg + 1] = make_float2(t.z, t.w);
        }
        x1v[10] = tile5[cpix];
#pragma unroll
        for (int p = 0; p < 11; ++p) x2v[p] = f2mul(swp[4], x1v[p]);
    }
#pragma unroll
    for (int dy = 0; dy < 3; ++dy)
#pragma unroll
        for (int dx = 0; dx < 3; ++dx) {
            if (dy == 1 && dx == 1) continue;
            const int npix = (ty + dy) * HTX + (tx + dx);
            const float2 wq = swp[dy * 3 + dx];
#pragma unroll
            for (int gg = 0; gg < 5; ++gg) {
                float4 t = tile4[gg][npix];
                x2v[2 * gg] = f2fma(wq, make_float2(t.x, t.y), x2v[2 * gg]);
                x2v[2 * gg + 1] = f2fma(wq, make_float2(t.z, t.w), x2v[2 * gg + 1]);
            }
            x2v[10] = f2fma(wq, tile5[npix], x2v[10]);
        }

    float acc[22];
#pragma unroll
    for (int k = 0; k < 22; ++k) acc[k] = x1[k];  // residual folded into init

    // merged path blocks: p = a*4 + b*2 + c
    tp_diag<4, 0>(x1, x2, acc, wcomb[0], wcomb[1]);
    tp_cross(x1, x2, acc, wcomb[2], wcomb[3], wcomb[4], wcomb[5]);
    tp_diag<6, 9>(x1, x2, acc, wcomb[6], wcomb[7]);

    // store (output layout: flat [N*9] then [N*13])
    const int gy = by * TY + ty, gx = bx * TX + tx;
    const int g = gy * W + gx;
#pragma unroll
    for (int k = 0; k < 9; ++k) out4[g * 9 + k] = acc[k];
#pragma unroll
    for (int k = 0; k < 13; ++k) out6[g * 13 + k] = acc[9 + k];
}

extern "C" void kernel_launch(void* const* d_in, const int* in_sizes, int n_in,
                              void* d_out, int out_size) {
    const float* f4 = (const float*)d_in[0];
    const float* f6 = (const float*)d_in[1];
    const float* sw = (const float*)d_in[2];  // spatial_weights [3,3]
    const float* wp = (const float*)d_in[3];  // w_paths [8]
    float* out = (float*)d_out;
    const size_t N = (size_t)H * W;

    dim3 grid(W / TX, H / TY);  // 24 x 192
    eq_spatial_tp_kernel<<<grid, NT>>>(f4, f6, sw, wp, out, out + N * 9);
}

// round 10
// speedup vs baseline: 6.7826x; 1.1434x over previous
#include <cuda_runtime.h>

// ============================================================================
// EquivariantSpatialConv: fused 3x3 replicate-pad depthwise spatial average
// + fully-connected CG tensor product (irreps 1x4e + 1x6e) + residual.
//
// R10: diagonal TP blocks accumulate UNWEIGHTED into z[22]; path weights are
// applied once per block (acc += w*z), deleting the 2 per-pair weight-MULs
// (~272 fma ops). Block order chosen for register liveness: diag44(z) ->
// acc=x1+w*z -> cross(acc) -> diag66(z, with l=4 inputs dead). I/O and
// spatial stage unchanged from R9 (pixel-outer LDG load, float4 smem, f32x2).
// ============================================================================

#define DEVHOST __host__ __device__

// ---------------- compile-time scalar math ----------------
DEVHOST constexpr double cfact(int n) {
    double r = 1.0;
    for (int i = 2; i <= n; ++i) r *= (double)i;
    return r;
}

DEVHOST constexpr double csqrt(double x) {
    if (x <= 0.0) return 0.0;
    double g = x > 1.0 ? x : 1.0;
    for (int it = 0; it < 48; ++it) g = 0.5 * (g + x / g);
    return g;
}

struct CD { double re, im; };
DEVHOST constexpr CD cmul(CD a, CD b) {
    return CD{a.re * b.re - a.im * b.im, a.re * b.im + a.im * b.re};
}
DEVHOST constexpr CD cconj(CD a) { return CD{a.re, -a.im}; }

DEVHOST constexpr double su2_cg(int j1, int j2, int j3, int m1, int m2, int m3) {
    if (m3 != m1 + m2) return 0.0;
    if (m1 < -j1 || m1 > j1 || m2 < -j2 || m2 > j2 || m3 < -j3 || m3 > j3) return 0.0;
    double pref0 = (2.0 * j3 + 1.0) * cfact(j1 + j2 - j3) * cfact(j1 - j2 + j3) *
                   cfact(-j1 + j2 + j3) / cfact(j1 + j2 + j3 + 1);
    double pref = csqrt(pref0 * cfact(j3 + m3) * cfact(j3 - m3) * cfact(j1 - m1) *
                        cfact(j1 + m1) * cfact(j2 - m2) * cfact(j2 + m2));
    int kmin = 0;
    if (-(j3 - j2 + m1) > kmin) kmin = -(j3 - j2 + m1);
    if (-(j3 - j1 - m2) > kmin) kmin = -(j3 - j1 - m2);
    int kmax = j1 + j2 - j3;
    if (j1 - m1 < kmax) kmax = j1 - m1;
    if (j2 + m2 < kmax) kmax = j2 + m2;
    double s = 0.0;
    for (int k = kmin; k <= kmax; ++k) {
        double d = cfact(k) * cfact(j1 + j2 - j3 - k) * cfact(j1 - m1 - k) *
                   cfact(j2 + m2 - k) * cfact(j3 - j2 + m1 + k) * cfact(j3 - j1 - m2 + k);
        s += ((k & 1) ? -1.0 : 1.0) / d;
    }
    return pref * s;
}

DEVHOST constexpr CD qent(int l, int r, int c) {
    constexpr double S2 = 0.70710678118654752440;
    int m = r - l;
    CD v{0.0, 0.0};
    if (m < 0) {
        if (c == l - m)      v = CD{S2, 0.0};
        else if (c == l + m) v = CD{0.0, -S2};
    } else if (m == 0) {
        if (c == l) v = CD{1.0, 0.0};
    } else {
        double sg = (m & 1) ? -1.0 : 1.0;
        if (c == l + m)      v = CD{sg * S2, 0.0};
        else if (c == l - m) v = CD{0.0, sg * S2};
    }
    int ph = l & 3;
    CD f = (ph == 0) ? CD{1, 0} : (ph == 1) ? CD{0, -1} : (ph == 2) ? CD{-1, 0} : CD{0, 1};
    return cmul(v, f);
}

DEVHOST constexpr double real_cg_entry(int l1, int l2, int l3, int a, int b, int c) {
    int d1 = a >= l1 ? a - l1 : l1 - a;
    int d2 = b >= l2 ? b - l2 : l2 - b;
    int d3 = c >= l3 ? c - l3 : l3 - c;
    CD sum{0.0, 0.0};
    int ni = d1 ? 2 : 1;
    int nk = d2 ? 2 : 1;
    for (int si = 0; si < ni; ++si) {
        int i = d1 ? (si ? l1 + d1 : l1 - d1) : l1;
        int m1 = i - l1;
        CD q1 = qent(l1, i, a);
        for (int sk = 0; sk < nk; ++sk) {
            int k = d2 ? (sk ? l2 + d2 : l2 - d2) : l2;
            int m2 = k - l2;
            int m3 = m1 + m2;
            if (m3 < -l3 || m3 > l3) continue;
            int am3 = m3 < 0 ? -m3 : m3;
            if (am3 != d3) continue;
            int n = l3 + m3;
            CD q2 = qent(l2, k, b);
            CD q3 = cconj(qent(l3, c, n));
            double C = su2_cg(l1, l2, l3, m1, m2, m3);
            CD t = cmul(cmul(q1, q2), q3);
            sum.re += t.re * C;
            sum.im += t.im * C;
        }
    }
    return sum.re;
}

template <int L1, int L2, int L3>
struct CGT {
    float v[2 * L1 + 1][2 * L2 + 1][2 * L3 + 1];
};

template <int L1, int L2, int L3>
DEVHOST constexpr CGT<L1, L2, L3> make_cg() {
    double tmp[2 * L1 + 1][2 * L2 + 1][2 * L3 + 1] = {};
    double ss = 0.0;
    for (int a = 0; a < 2 * L1 + 1; ++a)
        for (int b = 0; b < 2 * L2 + 1; ++b)
            for (int c = 0; c < 2 * L3 + 1; ++c) {
                double e = real_cg_entry(L1, L2, L3, a, b, c);
                tmp[a][b][c] = e;
                ss += e * e;
            }
    double inv = 1.0 / csqrt(ss);
    CGT<L1, L2, L3> r{};
    for (int a = 0; a < 2 * L1 + 1; ++a)
        for (int b = 0; b < 2 * L2 + 1; ++b)
            for (int c = 0; c < 2 * L3 + 1; ++c)
                r.v[a][b][c] = (float)(tmp[a][b][c] * inv);
    return r;
}

// Namespace-scope constexpr CG tensors (static storage: usable in constant
// expressions from any lambda depth inside function templates).
template <int L1, int L2, int L3>
inline constexpr CGT<L1, L2, L3> CG = make_cg<L1, L2, L3>();

// ---------------- compile-time unrolling helpers ----------------
template <int V> struct IC { static constexpr int value = V; };

template <int N, int I = 0, class F>
__device__ __forceinline__ void sfor(F&& f) {
    if constexpr (I < N) {
        f(IC<I>{});
        sfor<N, I + 1>(static_cast<F&&>(f));
    }
}

template <class T>
DEVHOST constexpr bool rowany(const T& t, int a, int b, int dk) {
    for (int k = 0; k < dk; ++k)
        if (t.v[a][b][k] != 0.0f) return true;
    return false;
}
template <class T>
DEVHOST constexpr bool rowany2(const T& t, int a, int b, int dk) {
    for (int k = 0; k < dk; ++k)
        if (t.v[a][b][k] != 0.0f || t.v[b][a][k] != 0.0f) return true;
    return false;
}
template <class T>
DEVHOST constexpr bool symk(const T& t, int a, int b, int dk) {
    for (int k = 0; k < dk; ++k)
        if (t.v[a][b][k] != t.v[b][a][k]) return false;
    return true;
}
template <class TA, class TB>
DEVHOST constexpr bool eqk(const TA& A, int i, int j, const TB& B, int bi, int bj, int dk) {
    for (int k = 0; k < dk; ++k)
        if (A.v[i][j][k] != B.v[bi][bj][k]) return false;
    return true;
}

// ---------------- packed f32x2 helpers ----------------
__device__ __forceinline__ float2 f2fma(float2 a, float2 b, float2 c) {
    float2 d;
    asm("fma.rn.f32x2 %0, %1, %2, %3;"
        : "=l"(*reinterpret_cast<unsigned long long*>(&d))
        : "l"(*reinterpret_cast<unsigned long long*>(&a)),
          "l"(*reinterpret_cast<unsigned long long*>(&b)),
          "l"(*reinterpret_cast<unsigned long long*>(&c)));
    return d;
}
__device__ __forceinline__ float2 f2mul(float2 a, float2 b) {
    float2 d;
    asm("mul.rn.f32x2 %0, %1, %2;"
        : "=l"(*reinterpret_cast<unsigned long long*>(&d))
        : "l"(*reinterpret_cast<unsigned long long*>(&a)),
          "l"(*reinterpret_cast<unsigned long long*>(&b)));
    return d;
}

// ---------------- tensor-product blocks ----------------
// Diagonal block (L,L,*): UNWEIGHTED accumulation into z[22]
// (z[0..8] <- CG<L,L,4>, z[9..21] <- CG<L,L,6>); weights applied by caller.
template <int L, int O>
__device__ __forceinline__ void tp_diag_z(const float* __restrict__ x1,
                                          const float* __restrict__ x2,
                                          float* __restrict__ z) {
    constexpr int D = 2 * L + 1;
    sfor<D>([&](auto I) {
        constexpr int i = decltype(I)::value;
        sfor<D>([&](auto J) {
            constexpr int j = decltype(J)::value;
            if constexpr (j >= i) {
                constexpr bool l0 = rowany2(CG<L, L, 4>, i, j, 9);
                constexpr bool l1 = rowany2(CG<L, L, 6>, i, j, 13);
                if constexpr (l0 || l1) {
                    if constexpr (i == j) {
                        float p = x1[O + i] * x2[O + i];
                        sfor<9>([&](auto K) {
                            constexpr int k = decltype(K)::value;
                            constexpr float cv = CG<L, L, 4>.v[i][i][k];
                            if constexpr (cv != 0.0f) z[k] = __fmaf_rn(cv, p, z[k]);
                        });
                        sfor<13>([&](auto K) {
                            constexpr int k = decltype(K)::value;
                            constexpr float cv = CG<L, L, 6>.v[i][i][k];
                            if constexpr (cv != 0.0f) z[9 + k] = __fmaf_rn(cv, p, z[9 + k]);
                        });
                    } else if constexpr (symk(CG<L, L, 4>, i, j, 9) && symk(CG<L, L, 6>, i, j, 13)) {
                        float s = __fmaf_rn(x1[O + j], x2[O + i], x1[O + i] * x2[O + j]);
                        sfor<9>([&](auto K) {
                            constexpr int k = decltype(K)::value;
                            constexpr float cv = CG<L, L, 4>.v[i][j][k];
                            if constexpr (cv != 0.0f) z[k] = __fmaf_rn(cv, s, z[k]);
                        });
                        sfor<13>([&](auto K) {
                            constexpr int k = decltype(K)::value;
                            constexpr float cv = CG<L, L, 6>.v[i][j][k];
                            if constexpr (cv != 0.0f) z[9 + k] = __fmaf_rn(cv, s, z[9 + k]);
                        });
                    } else {
                        // fallback (not expected for even l1+l2+l3): both orders
                        float p1 = x1[O + i] * x2[O + j];
                        float p2 = x1[O + j] * x2[O + i];
                        sfor<9>([&](auto K) {
                            constexpr int k = decltype(K)::value;
                            constexpr float c1 = CG<L, L, 4>.v[i][j][k];
                            constexpr float c2 = CG<L, L, 4>.v[j][i][k];
                            if constexpr (c1 != 0.0f) z[k] = __fmaf_rn(c1, p1, z[k]);
                            if constexpr (c2 != 0.0f) z[k] = __fmaf_rn(c2, p2, z[k]);
                        });
                        sfor<13>([&](auto K) {
                            constexpr int k = decltype(K)::value;
                            constexpr float c1 = CG<L, L, 6>.v[i][j][k];
                            constexpr float c2 = CG<L, L, 6>.v[j][i][k];
                            if constexpr (c1 != 0.0f) z[9 + k] = __fmaf_rn(c1, p1, z[9 + k]);
                            if constexpr (c2 != 0.0f) z[9 + k] = __fmaf_rn(c2, p2, z[9 + k]);
                        });
                    }
                }
            }
        });
    });
}

// Cross block: paths (4,6,c) and (6,4,c), merged when the CG tensors
// coincide under exchange (verified at compile time). Weighted into acc.
__device__ __forceinline__ void tp_cross(const float* __restrict__ x1,
                                         const float* __restrict__ x2,
                                         float* __restrict__ acc,
                                         float wA0, float wA1, float wB0, float wB1) {
    sfor<9>([&](auto I) {
        constexpr int i = decltype(I)::value;
        sfor<13>([&](auto J) {
            constexpr int j = decltype(J)::value;
            constexpr bool a0 = rowany(CG<4, 6, 4>, i, j, 9);
            constexpr bool b0 = rowany(CG<6, 4, 4>, j, i, 9);
            constexpr bool a1 = rowany(CG<4, 6, 6>, i, j, 13);
            constexpr bool b1 = rowany(CG<6, 4, 6>, j, i, 13);
            if constexpr (a0 || b0 || a1 || b1) {
                float p1 = x1[i] * x2[9 + j];
                float p2 = x2[i] * x1[9 + j];
                if constexpr (a0 || b0) {
                    if constexpr (a0 && b0 && eqk(CG<4, 6, 4>, i, j, CG<6, 4, 4>, j, i, 9)) {
                        float u = __fmaf_rn(wB0, p2, p1 * wA0);
                        sfor<9>([&](auto K) {
                            constexpr int k = decltype(K)::value;
                            constexpr float cv = CG<4, 6, 4>.v[i][j][k];
                            if constexpr (cv != 0.0f) acc[k] = __fmaf_rn(cv, u, acc[k]);
                        });
                    } else {
                        if constexpr (a0) {
                            float t1 = p1 * wA0;
                            sfor<9>([&](auto K) {
                                constexpr int k = decltype(K)::value;
                                constexpr float cv = CG<4, 6, 4>.v[i][j][k];
                                if constexpr (cv != 0.0f) acc[k] = __fmaf_rn(cv, t1, acc[k]);
                            });
                        }
                        if constexpr (b0) {
                            float t2 = p2 * wB0;
                            sfor<9>([&](auto K) {
                                constexpr int k = decltype(K)::value;
                                constexpr float cv = CG<6, 4, 4>.v[j][i][k];
                                if constexpr (cv != 0.0f) acc[k] = __fmaf_rn(cv, t2, acc[k]);
                            });
                        }
                    }
                }
                if constexpr (a1 || b1) {
                    if constexpr (a1 && b1 && eqk(CG<4, 6, 6>, i, j, CG<6, 4, 6>, j, i, 13)) {
                        float u = __fmaf_rn(wB1, p2, p1 * wA1);
                        sfor<13>([&](auto K) {
                            constexpr int k = decltype(K)::value;
                            constexpr float cv = CG<4, 6, 6>.v[i][j][k];
                            if constexpr (cv != 0.0f) acc[9 + k] = __fmaf_rn(cv, u, acc[9 + k]);
                        });
                    } else {
                        if constexpr (a1) {
                            float t1 = p1 * wA1;
                            sfor<13>([&](auto K) {
                                constexpr int k = decltype(K)::value;
                                constexpr float cv = CG<4, 6, 6>.v[i][j][k];
                                if constexpr (cv != 0.0f) acc[9 + k] = __fmaf_rn(cv, t1, acc[9 + k]);
                            });
                        }
                        if constexpr (b1) {
                            float t2 = p2 * wB1;
                            sfor<13>([&](auto K) {
                                constexpr int k = decltype(K)::value;
                                constexpr float cv = CG<6, 4, 6>.v[j][i][k];
                                if constexpr (cv != 0.0f) acc[9 + k] = __fmaf_rn(cv, t2, acc[9 + k]);
                            });
                        }
                    }
                }
            }
        });
    });
}

// ---------------- kernel ----------------
constexpr int H = 768, W = 768;
constexpr int TX = 32, TY = 4;             // 128-thread tile
constexpr int NT = TX * TY;                // 128
constexpr int HTX = TX + 2, HTY = TY + 2;  // 34 x 6 haloed tile
constexpr int NPIX = HTX * HTY;            // 204

__global__ void __launch_bounds__(NT, 7) eq_spatial_tp_kernel(
    const float* __restrict__ f4, const float* __restrict__ f6,
    const float* __restrict__ sw, const float* __restrict__ wp,
    float* __restrict__ out4, float* __restrict__ out6) {
    // float4-group, pixel-major smem: groups 0-4 hold ch 4g..4g+3, group 5 ch 20-21.
    __shared__ float4 tile4[5][NPIX];   // 16320 B
    __shared__ float2 tile5[NPIX];      // 1632 B -> 17952 B total, 7 CTAs = 126 KB

    const int tid = threadIdx.x;
    const int bx = blockIdx.x, by = blockIdx.y;
    const int gx0 = bx * TX - 1, gy0 = by * TY - 1;

    // hoist weight loads so their latency overlaps the tile load
    float2 swp[9];
#pragma unroll
    for (int q = 0; q < 9; ++q) {
        float s = sw[q];
        swp[q] = make_float2(s, s);
    }
    float wcomb[8];
#pragma unroll
    for (int p = 0; p < 8; ++p) wcomb[p] = 0.5f * wp[p];  // ALPHA = 1/sqrt(4)

    // ---- pixel-outer haloed-tile load (2 pixels/thread, compile-time offsets) ----
#pragma unroll
    for (int pix = tid; pix < NPIX; pix += NT) {
        int r = pix / HTX, c = pix - r * HTX;
        int gy = gy0 + r; gy = gy < 0 ? 0 : (gy > H - 1 ? H - 1 : gy);
        int gx = gx0 + c; gx = gx < 0 ? 0 : (gx > W - 1 ? W - 1 : gx);
        int g = gy * W + gx;
        const float* p4 = f4 + g * 9;
        const float* p6 = f6 + g * 13;
        float v[22];
#pragma unroll
        for (int ch = 0; ch < 9; ++ch) v[ch] = p4[ch];
#pragma unroll
        for (int ch = 0; ch < 13; ++ch) v[9 + ch] = p6[ch];
#pragma unroll
        for (int gg = 0; gg < 5; ++gg)
            tile4[gg][pix] = make_float4(v[4 * gg], v[4 * gg + 1], v[4 * gg + 2], v[4 * gg + 3]);
        tile5[pix] = make_float2(v[20], v[21]);
    }
    __syncthreads();

    const int tx = tid & 31, ty = tid >> 5;

    // x1 = center features; x2 = weighted 3x3 neighbor average (packed f32x2)
    __align__(16) float x1[22];
    __align__(8) float x2[22];
    float2* x1v = reinterpret_cast<float2*>(x1);
    float2* x2v = reinterpret_cast<float2*>(x2);
    {
        const int cpix = (ty + 1) * HTX + (tx + 1);
#pragma unroll
        for (int gg = 0; gg < 5; ++gg) {
            float4 t = tile4[gg][cpix];
            x1v[2 * gg] = make_float2(t.x, t.y);
            x1v[2 * gg + 1] = make_float2(t.z, t.w);
        }
        x1v[10] = tile5[cpix];
#pragma unroll
        for (int p = 0; p < 11; ++p) x2v[p] = f2mul(swp[4], x1v[p]);
    }
#pragma unroll
    for (int dy = 0; dy < 3; ++dy)
#pragma unroll
        for (int dx = 0; dx < 3; ++dx) {
            if (dy == 1 && dx == 1) continue;
            const int npix = (ty + dy) * HTX + (tx + dx);
            const float2 wq = swp[dy * 3 + dx];
#pragma unroll
            for (int gg = 0; gg < 5; ++gg) {
                float4 t = tile4[gg][npix];
                x2v[2 * gg] = f2fma(wq, make_float2(t.x, t.y), x2v[2 * gg]);
                x2v[2 * gg + 1] = f2fma(wq, make_float2(t.z, t.w), x2v[2 * gg + 1]);
            }
            x2v[10] = f2fma(wq, tile5[npix], x2v[10]);
        }

    // ---- TP, ordered for register liveness ----
    float acc[22];
    {
        // diag44 unweighted -> z; acc born as x1 + w*z (z dies into acc)
        float z[22];
#pragma unroll
        for (int k = 0; k < 22; ++k) z[k] = 0.0f;
        tp_diag_z<4, 0>(x1, x2, z);
#pragma unroll
        for (int k = 0; k < 9; ++k) acc[k] = __fmaf_rn(wcomb[0], z[k], x1[k]);
#pragma unroll
        for (int k = 0; k < 13; ++k) acc[9 + k] = __fmaf_rn(wcomb[1], z[9 + k], x1[9 + k]);
    }

    // cross block (merged), weighted into acc
    tp_cross(x1, x2, acc, wcomb[2], wcomb[3], wcomb[4], wcomb[5]);

    {
        // diag66 unweighted -> z (x1[0..8]/x2[0..8] dead by now)
        float z[22];
#pragma unroll
        for (int k = 0; k < 22; ++k) z[k] = 0.0f;
        tp_diag_z<6, 9>(x1, x2, z);
#pragma unroll
        for (int k = 0; k < 9; ++k) acc[k] = __fmaf_rn(wcomb[6], z[k], acc[k]);
#pragma unroll
        for (int k = 0; k < 13; ++k) acc[9 + k] = __fmaf_rn(wcomb[7], z[9 + k], acc[9 + k]);
    }

    // store (output layout: flat [N*9] then [N*13])
    const int gy = by * TY + ty, gx = bx * TX + tx;
    const int g = gy * W + gx;
#pragma unroll
    for (int k = 0; k < 9; ++k) out4[g * 9 + k] = acc[k];
#pragma unroll
    for (int k = 0; k < 13; ++k) out6[g * 13 + k] = acc[9 + k];
}

extern "C" void kernel_launch(void* const* d_in, const int* in_sizes, int n_in,
                              void* d_out, int out_size) {
    const float* f4 = (const float*)d_in[0];
    const float* f6 = (const float*)d_in[1];
    const float* sw = (const float*)d_in[2];  // spatial_weights [3,3]
    const float* wp = (const float*)d_in[3];  // w_paths [8]
    float* out = (float*)d_out;
    const size_t N = (size_t)H * W;

    dim3 grid(W / TX, H / TY);  // 24 x 192
    eq_spatial_tp_kernel<<<grid, NT>>>(f4, f6, sw, wp, out, out + N * 9);
}